// round 1
// baseline (speedup 1.0000x reference)
#include <cuda_runtime.h>
#include <math.h>

#define BB   64
#define DD   4096
#define HH   32
#define HDIM 128
#define PBS  16
#define MBSN 32
#define DFF  16384

// ---------------- device scratch (no allocations allowed) ----------------
__device__ float g_h  [BB * DD];
__device__ float g_q  [BB * DD];
__device__ float g_k  [BB * DD];
__device__ float g_v  [BB * DD];
__device__ float g_att[BB * DD];
__device__ float g_x2 [BB * DD];
__device__ float g_h2 [BB * DD];
__device__ float g_p0 [BB * DD];
__device__ float g_p1 [BB * DD];
__device__ float g_ff1[BB * DFF];
__device__ float g_ff3[BB * DFF];
__device__ float g_gate[BB * DFF];

// ---------------- RMSNorm: out = x * rsqrt(mean(x^2)+eps) * g ----------------
__global__ __launch_bounds__(256) void rmsnorm_kernel(
    const float* __restrict__ x, const float* __restrict__ g, float* __restrict__ out)
{
    int row = blockIdx.x, tid = threadIdx.x;
    const float4* xr = (const float4*)(x + (size_t)row * DD);
    const float4* gr = (const float4*)g;
    float4 v[4];
    float ss = 0.f;
#pragma unroll
    for (int i = 0; i < 4; i++) {
        v[i] = xr[tid + 256 * i];
        ss += v[i].x * v[i].x + v[i].y * v[i].y + v[i].z * v[i].z + v[i].w * v[i].w;
    }
#pragma unroll
    for (int o = 16; o; o >>= 1) ss += __shfl_xor_sync(0xffffffffu, ss, o);
    __shared__ float sred[8];
    if ((tid & 31) == 0) sred[tid >> 5] = ss;
    __syncthreads();
    float tot = 0.f;
#pragma unroll
    for (int i = 0; i < 8; i++) tot += sred[i];
    float inv = rsqrtf(tot / (float)DD + 1e-5f);
    float4* orow = (float4*)(out + (size_t)row * DD);
#pragma unroll
    for (int i = 0; i < 4; i++) {
        float4 gv = gr[tid + 256 * i];
        float4 o4;
        o4.x = v[i].x * inv * gv.x;
        o4.y = v[i].y * inv * gv.y;
        o4.z = v[i].z * inv * gv.z;
        o4.w = v[i].w * inv * gv.w;
        orow[tid + 256 * i] = o4;
    }
}

// ---------------- SGEMM: C[64,N] = A[64,K] @ W[N,K]^T (tiled, multi-matrix) --
struct GemmP {
    const float* A;
    const float* Wm[3];
    float*       Cm[3];
    int lda;
    int ldc;
    int nbpm;        // blocks (of 64 cols) per matrix slot
    int k0[3], k1[3];
};

__global__ __launch_bounds__(256) void sgemm_kernel(GemmP p)
{
    int mat = blockIdx.x / p.nbpm;
    int nb  = blockIdx.x % p.nbpm;
    const float* W = p.Wm[mat];
    float*       C = p.Cm[mat];
    int n0 = nb * 64;
    int k0 = p.k0[mat], k1 = p.k1[mat];

    __shared__ float As[16][68];
    __shared__ float Bs[16][68];

    int tid  = threadIdx.x;
    int tx   = tid & 15;          // n-group
    int ty   = tid >> 4;          // m-group
    int lrow = tid >> 2;          // load row 0..63
    int lcol = (tid & 3) << 2;    // load col 0,4,8,12

    const float* Ap = p.A + (size_t)lrow * p.lda + k0 + lcol;
    const float* Wp = W + (size_t)(n0 + lrow) * p.lda + k0 + lcol;

    float acc[4][4] = {};

    for (int k = k0; k < k1; k += 16) {
        float4 av = *(const float4*)Ap;
        float4 bv = *(const float4*)Wp;
        As[lcol + 0][lrow] = av.x;
        As[lcol + 1][lrow] = av.y;
        As[lcol + 2][lrow] = av.z;
        As[lcol + 3][lrow] = av.w;
        Bs[lcol + 0][lrow] = bv.x;
        Bs[lcol + 1][lrow] = bv.y;
        Bs[lcol + 2][lrow] = bv.z;
        Bs[lcol + 3][lrow] = bv.w;
        __syncthreads();
#pragma unroll
        for (int kk = 0; kk < 16; kk++) {
            float4 a4 = *(const float4*)&As[kk][ty << 2];
            float4 b4 = *(const float4*)&Bs[kk][tx << 2];
            float ar[4] = {a4.x, a4.y, a4.z, a4.w};
            float br[4] = {b4.x, b4.y, b4.z, b4.w};
#pragma unroll
            for (int i = 0; i < 4; i++)
#pragma unroll
                for (int j = 0; j < 4; j++)
                    acc[i][j] = fmaf(ar[i], br[j], acc[i][j]);
        }
        __syncthreads();
        Ap += 16;
        Wp += 16;
    }

#pragma unroll
    for (int i = 0; i < 4; i++) {
        float4 r = {acc[i][0], acc[i][1], acc[i][2], acc[i][3]};
        *(float4*)&C[(size_t)(ty * 4 + i) * p.ldc + n0 + tx * 4] = r;
    }
}

// ---------------- paged flash-decode attention ----------------
// One block per (head, batch). The newly decoded token (position ctx-1) is
// taken from g_k/g_v instead of the heap (equivalent to reshape_and_cache).
__global__ __launch_bounds__(128) void attention_kernel(
    const float* __restrict__ kheap, const float* __restrict__ vheap,
    const int*   __restrict__ btab,  const int*  __restrict__ clens,
    const float* __restrict__ scale_p)
{
    int hh = blockIdx.x, b = blockIdx.y;
    int tid = threadIdx.x, lane = tid & 31, w = tid >> 5;
    int ctx = clens[b];
    float scale = scale_p[0];

    const float4* q4 = (const float4*)(g_q + (size_t)b * DD + hh * HDIM);
    float4 qv = q4[lane];

    float m = -1e30f, l = 0.f;
    float4 acc = {0.f, 0.f, 0.f, 0.f};
    const int last = ctx - 1;

    for (int s = w; s < ctx; s += 4) {
        const float *kp, *vp;
        if (s == last) {
            kp = g_k + (size_t)b * DD + hh * HDIM;
            vp = g_v + (size_t)b * DD + hh * HDIM;
        } else {
            int blk = btab[b * MBSN + (s >> 4)];
            size_t base = (((size_t)blk * HH + hh) * PBS + (s & 15)) * HDIM;
            kp = kheap + base;
            vp = vheap + base;
        }
        float4 kv = *(const float4*)(kp + lane * 4);
        float sc = qv.x * kv.x + qv.y * kv.y + qv.z * kv.z + qv.w * kv.w;
#pragma unroll
        for (int o = 16; o; o >>= 1) sc += __shfl_xor_sync(0xffffffffu, sc, o);
        sc *= scale;
        float mn   = fmaxf(m, sc);
        float corr = expf(m - mn);
        float pw   = expf(sc - mn);
        l = l * corr + pw;
        float4 vv = *(const float4*)(vp + lane * 4);
        acc.x = fmaf(pw, vv.x, acc.x * corr);
        acc.y = fmaf(pw, vv.y, acc.y * corr);
        acc.z = fmaf(pw, vv.z, acc.z * corr);
        acc.w = fmaf(pw, vv.w, acc.w * corr);
        m = mn;
    }

    __shared__ float sm_m[4], sm_l[4];
    __shared__ float sm_acc[4][HDIM];
    if (lane == 0) { sm_m[w] = m; sm_l[w] = l; }
    ((float4*)sm_acc[w])[lane] = acc;
    __syncthreads();

    int d = tid;  // 0..127
    float M = fmaxf(fmaxf(sm_m[0], sm_m[1]), fmaxf(sm_m[2], sm_m[3]));
    float L = 0.f, O = 0.f;
#pragma unroll
    for (int i = 0; i < 4; i++) {
        float e = expf(sm_m[i] - M);
        L += sm_l[i] * e;
        O += sm_acc[i][d] * e;
    }
    g_att[(size_t)b * DD + hh * HDIM + d] = O / L;
}

// ---------------- x2 = p0+p1+resid ; h2 = rmsnorm(x2)*g ----------------
__global__ __launch_bounds__(256) void addreduce_rms_kernel(
    const float* __restrict__ resid, const float* __restrict__ g,
    float* __restrict__ xout, float* __restrict__ hout)
{
    int row = blockIdx.x, tid = threadIdx.x;
    const float4* a4 = (const float4*)(g_p0 + (size_t)row * DD);
    const float4* b4 = (const float4*)(g_p1 + (size_t)row * DD);
    const float4* r4 = (const float4*)(resid + (size_t)row * DD);
    const float4* gr = (const float4*)g;
    float4 v[4];
    float ss = 0.f;
#pragma unroll
    for (int i = 0; i < 4; i++) {
        int idx = tid + 256 * i;
        float4 a = a4[idx], b = b4[idx], r = r4[idx];
        v[i].x = a.x + b.x + r.x;
        v[i].y = a.y + b.y + r.y;
        v[i].z = a.z + b.z + r.z;
        v[i].w = a.w + b.w + r.w;
        ss += v[i].x * v[i].x + v[i].y * v[i].y + v[i].z * v[i].z + v[i].w * v[i].w;
    }
#pragma unroll
    for (int o = 16; o; o >>= 1) ss += __shfl_xor_sync(0xffffffffu, ss, o);
    __shared__ float sred[8];
    if ((tid & 31) == 0) sred[tid >> 5] = ss;
    __syncthreads();
    float tot = 0.f;
#pragma unroll
    for (int i = 0; i < 8; i++) tot += sred[i];
    float inv = rsqrtf(tot / (float)DD + 1e-5f);
    float4* xo = (float4*)(xout + (size_t)row * DD);
    float4* ho = (float4*)(hout + (size_t)row * DD);
#pragma unroll
    for (int i = 0; i < 4; i++) {
        int idx = tid + 256 * i;
        xo[idx] = v[i];
        float4 gv = gr[idx];
        float4 o4;
        o4.x = v[i].x * inv * gv.x;
        o4.y = v[i].y * inv * gv.y;
        o4.z = v[i].z * inv * gv.z;
        o4.w = v[i].w * inv * gv.w;
        ho[idx] = o4;
    }
}

// ---------------- gate = silu(ff1) * ff3 ----------------
__global__ __launch_bounds__(256) void silu_mul_kernel()
{
    int idx = blockIdx.x * 256 + threadIdx.x;   // float4 index, 262144 total
    float4 a = ((const float4*)g_ff1)[idx];
    float4 c = ((const float4*)g_ff3)[idx];
    float4 o;
    o.x = a.x / (1.f + expf(-a.x)) * c.x;
    o.y = a.y / (1.f + expf(-a.y)) * c.y;
    o.z = a.z / (1.f + expf(-a.z)) * c.z;
    o.w = a.w / (1.f + expf(-a.w)) * c.w;
    ((float4*)g_gate)[idx] = o;
}

// ---------------- out = p0 + p1 + resid ----------------
__global__ __launch_bounds__(256) void final_add_kernel(
    const float* __restrict__ resid, float* __restrict__ out)
{
    int idx = blockIdx.x * 256 + threadIdx.x;   // float4 index, 65536 total
    float4 a = ((const float4*)g_p0)[idx];
    float4 b = ((const float4*)g_p1)[idx];
    float4 r = ((const float4*)resid)[idx];
    float4 o;
    o.x = a.x + b.x + r.x;
    o.y = a.y + b.y + r.y;
    o.z = a.z + b.z + r.z;
    o.w = a.w + b.w + r.w;
    ((float4*)out)[idx] = o;
}

// ---------------- host driver ----------------
extern "C" void kernel_launch(void* const* d_in, const int* in_sizes, int n_in,
                              void* d_out, int out_size)
{
    const float* x     = (const float*)d_in[0];
    const float* kheap = (const float*)d_in[1];
    const float* vheap = (const float*)d_in[2];
    const int*   btab  = (const int*)d_in[3];
    const int*   clens = (const int*)d_in[5];
    const float* scale = (const float*)d_in[9];
    const float* Wq    = (const float*)d_in[13];
    const float* Wk    = (const float*)d_in[14];
    const float* Wv    = (const float*)d_in[15];
    const float* Wo    = (const float*)d_in[16];
    const float* W1    = (const float*)d_in[17];
    const float* W2    = (const float*)d_in[18];
    const float* W3    = (const float*)d_in[19];
    const float* g1    = (const float*)d_in[20];
    const float* g2    = (const float*)d_in[21];
    float* out = (float*)d_out;

    float *h, *q, *k, *v, *att, *x2, *h2, *p0, *p1, *ff1, *ff3, *gate;
    cudaGetSymbolAddress((void**)&h,   g_h);
    cudaGetSymbolAddress((void**)&q,   g_q);
    cudaGetSymbolAddress((void**)&k,   g_k);
    cudaGetSymbolAddress((void**)&v,   g_v);
    cudaGetSymbolAddress((void**)&att, g_att);
    cudaGetSymbolAddress((void**)&x2,  g_x2);
    cudaGetSymbolAddress((void**)&h2,  g_h2);
    cudaGetSymbolAddress((void**)&p0,  g_p0);
    cudaGetSymbolAddress((void**)&p1,  g_p1);
    cudaGetSymbolAddress((void**)&ff1, g_ff1);
    cudaGetSymbolAddress((void**)&ff3, g_ff3);
    cudaGetSymbolAddress((void**)&gate, g_gate);

    // 1) h = rmsnorm(x) * g1
    rmsnorm_kernel<<<BB, 256>>>(x, g1, h);

    // 2) q,k,v = h @ {Wq,Wk,Wv}^T   (one fused launch, 192 blocks)
    {
        GemmP p;
        p.A = h; p.lda = DD; p.ldc = DD; p.nbpm = DD / 64;
        p.Wm[0] = Wq; p.Wm[1] = Wk; p.Wm[2] = Wv;
        p.Cm[0] = q;  p.Cm[1] = k;  p.Cm[2] = v;
        for (int i = 0; i < 3; i++) { p.k0[i] = 0; p.k1[i] = DD; }
        sgemm_kernel<<<3 * (DD / 64), 256>>>(p);
    }

    // 3) paged attention (reads g_q/g_k/g_v globals, writes g_att)
    attention_kernel<<<dim3(HH, BB), 128>>>(kheap, vheap, btab, clens, scale);

    // 4) att @ Wo^T, split-K=2 into p0/p1
    {
        GemmP p;
        p.A = att; p.lda = DD; p.ldc = DD; p.nbpm = DD / 64;
        p.Wm[0] = Wo; p.Wm[1] = Wo; p.Wm[2] = Wo;
        p.Cm[0] = p0; p.Cm[1] = p1; p.Cm[2] = p0;
        p.k0[0] = 0;       p.k1[0] = DD / 2;
        p.k0[1] = DD / 2;  p.k1[1] = DD;
        p.k0[2] = 0;       p.k1[2] = 0;
        sgemm_kernel<<<2 * (DD / 64), 256>>>(p);
    }

    // 5) x2 = p0+p1+x ; h2 = rmsnorm(x2) * g2
    addreduce_rms_kernel<<<BB, 256>>>(x, g2, x2, h2);

    // 6) ff1 = h2 @ W1^T, ff3 = h2 @ W3^T  (fused, 512 blocks)
    {
        GemmP p;
        p.A = h2; p.lda = DD; p.ldc = DFF; p.nbpm = DFF / 64;
        p.Wm[0] = W1; p.Wm[1] = W3; p.Wm[2] = W1;
        p.Cm[0] = ff1; p.Cm[1] = ff3; p.Cm[2] = ff1;
        for (int i = 0; i < 3; i++) { p.k0[i] = 0; p.k1[i] = DD; }
        sgemm_kernel<<<2 * (DFF / 64), 256>>>(p);
    }

    // 7) gate = silu(ff1) * ff3
    silu_mul_kernel<<<(BB * DFF) / 4 / 256, 256>>>();

    // 8) gate @ W2^T, split-K=2 into p0/p1
    {
        GemmP p;
        p.A = gate; p.lda = DFF; p.ldc = DD; p.nbpm = DD / 64;
        p.Wm[0] = W2; p.Wm[1] = W2; p.Wm[2] = W2;
        p.Cm[0] = p0; p.Cm[1] = p1; p.Cm[2] = p0;
        p.k0[0] = 0;        p.k1[0] = DFF / 2;
        p.k0[1] = DFF / 2;  p.k1[1] = DFF;
        p.k0[2] = 0;        p.k1[2] = 0;
        sgemm_kernel<<<2 * (DD / 64), 256>>>(p);
    }

    // 9) out = p0 + p1 + x2
    final_add_kernel<<<(BB * DD) / 4 / 256, 256>>>(x2, out);
}

// round 3
// speedup vs baseline: 1.7273x; 1.7273x over previous
#include <cuda_runtime.h>
#include <cuda_bf16.h>
#include <math.h>
#include <stdint.h>

#define BB   64
#define DD   4096
#define HH   32
#define HDIM 128
#define PBS  16
#define MBSN 32
#define DFF  16384

// ---------------- device scratch ----------------
__device__ float g_h  [BB * DD];
__device__ float g_q  [BB * DD];
__device__ float g_k  [BB * DD];
__device__ float g_v  [BB * DD];
__device__ float g_att[BB * DD];
__device__ float g_x2 [BB * DD];
__device__ float g_h2 [BB * DD];
__device__ float g_p0 [BB * DD];
__device__ float g_p1 [BB * DD];
__device__ float g_p2 [BB * DD];
__device__ float g_p3 [BB * DD];
__device__ float g_ff1[BB * DFF];
__device__ float g_ff3[BB * DFF];
__device__ float g_gate[BB * DFF];

// ---------------- PTX helpers ----------------
#define LDSM4(r0, r1, r2, r3, addr)                                          \
    asm volatile("ldmatrix.sync.aligned.m8n8.x4.shared.b16 {%0,%1,%2,%3}, [%4];" \
                 : "=r"(r0), "=r"(r1), "=r"(r2), "=r"(r3) : "r"(addr))

#define MMA16816(d, a0, a1, a2, a3, b0, b1)                                   \
    asm volatile("mma.sync.aligned.m16n8k16.row.col.f32.bf16.bf16.f32 "       \
                 "{%0,%1,%2,%3},{%4,%5,%6,%7},{%8,%9},{%0,%1,%2,%3};"         \
                 : "+f"(d[0]), "+f"(d[1]), "+f"(d[2]), "+f"(d[3])             \
                 : "r"(a0), "r"(a1), "r"(a2), "r"(a3), "r"(b0), "r"(b1))

// split fp32 -> (hi, lo) bf16 and pack 4 consecutive into uint2 each
__device__ __forceinline__ void cvt_split4(float4 v, uint2& uh, uint2& ul)
{
    __nv_bfloat16 h0 = __float2bfloat16_rn(v.x);
    __nv_bfloat16 h1 = __float2bfloat16_rn(v.y);
    __nv_bfloat16 h2 = __float2bfloat16_rn(v.z);
    __nv_bfloat16 h3 = __float2bfloat16_rn(v.w);
    __nv_bfloat16 l0 = __float2bfloat16_rn(v.x - __bfloat162float(h0));
    __nv_bfloat16 l1 = __float2bfloat16_rn(v.y - __bfloat162float(h1));
    __nv_bfloat16 l2 = __float2bfloat16_rn(v.z - __bfloat162float(h2));
    __nv_bfloat16 l3 = __float2bfloat16_rn(v.w - __bfloat162float(h3));
    __nv_bfloat162 ph01 = __halves2bfloat162(h0, h1);
    __nv_bfloat162 ph23 = __halves2bfloat162(h2, h3);
    __nv_bfloat162 pl01 = __halves2bfloat162(l0, l1);
    __nv_bfloat162 pl23 = __halves2bfloat162(l2, l3);
    uh.x = *(unsigned int*)&ph01; uh.y = *(unsigned int*)&ph23;
    ul.x = *(unsigned int*)&pl01; ul.y = *(unsigned int*)&pl23;
}

// ---------------- bf16-split tensor-core GEMM ----------------
// C[64, N] = A[64, K] @ W[N, K]^T   (per job; fused multi-job launches)
// Block tile: M=64, N=128, Kc=64. 256 threads = 8 warps (2 M x 4 N).
struct Job { const float* W; float* C; int k0, k1; };
struct GP  { const float* A; int lda; int ldc; int nbpj; Job jobs[4]; };

#define KPAD 72   // 64 + 8 halves pad

__global__ __launch_bounds__(256) void bf16gemm_kernel(GP p)
{
    int job = blockIdx.x / p.nbpj;
    int nb  = blockIdx.x % p.nbpj;
    const float* W = p.jobs[job].W;
    float*       C = p.jobs[job].C;
    const int k0j = p.jobs[job].k0, k1j = p.jobs[job].k1;
    const int n0  = nb * 128;

    extern __shared__ __nv_bfloat16 smem_bf[];
    __nv_bfloat16* smA = smem_bf;                 // [2][64][KPAD]  (hi, lo)
    __nv_bfloat16* smB = smem_bf + 2 * 64 * KPAD; // [2][128][KPAD]

    const int tid = threadIdx.x, lane = tid & 31, w = tid >> 5;
    const int wm = w & 1, wn = w >> 1;

    // ldmatrix per-lane address components
    const int arow = (lane & 7) + (lane & 8);
    const int acol = (lane & 16) >> 1;
    const int brow = (lane & 7) + ((lane & 16) >> 1);
    const int bcol = lane & 8;

    float acc[2][4][4];
#pragma unroll
    for (int i = 0; i < 2; i++)
#pragma unroll
        for (int j = 0; j < 4; j++)
#pragma unroll
            for (int t = 0; t < 4; t++) acc[i][j][t] = 0.f;

    const int lrowA = tid >> 2, lcolA = (tid & 3) * 16;
    const int lrowW = tid >> 1, lcolW = (tid & 1) * 32;
    const float* Arow = p.A + (size_t)lrowA * p.lda + lcolA;
    const float* Wrow = W + (size_t)(n0 + lrowW) * p.lda + lcolW;

    __nv_bfloat16* sa_h = smA + lrowA * KPAD + lcolA;
    __nv_bfloat16* sa_l = sa_h + 64 * KPAD;
    __nv_bfloat16* sb_h = smB + lrowW * KPAD + lcolW;
    __nv_bfloat16* sb_l = sb_h + 128 * KPAD;

    unsigned int a_base[2], b_base[2];
#pragma unroll
    for (int mi = 0; mi < 2; mi++)
        a_base[mi] = (unsigned int)__cvta_generic_to_shared(
            smA + (wm * 32 + mi * 16 + arow) * KPAD + acol);
#pragma unroll
    for (int nj = 0; nj < 2; nj++)
        b_base[nj] = (unsigned int)__cvta_generic_to_shared(
            smB + (wn * 32 + nj * 16 + brow) * KPAD + bcol);
    const unsigned int A_LO = 64 * KPAD * 2;    // bytes
    const unsigned int B_LO = 128 * KPAD * 2;

    for (int kc = k0j; kc < k1j; kc += 64) {
        // ---- load + convert chunk ----
#pragma unroll
        for (int i = 0; i < 4; i++) {
            float4 v = *(const float4*)(Arow + kc + 4 * i);
            uint2 uh, ul;
            cvt_split4(v, uh, ul);
            *(uint2*)(sa_h + 4 * i) = uh;
            *(uint2*)(sa_l + 4 * i) = ul;
        }
#pragma unroll
        for (int i = 0; i < 8; i++) {
            float4 v = *(const float4*)(Wrow + kc + 4 * i);
            uint2 uh, ul;
            cvt_split4(v, uh, ul);
            *(uint2*)(sb_h + 4 * i) = uh;
            *(uint2*)(sb_l + 4 * i) = ul;
        }
        __syncthreads();

        // ---- compute 4 k-steps of 16 ----
#pragma unroll
        for (int ks = 0; ks < 4; ks++) {
            const unsigned int koff = ks * 16 * 2;   // bytes along k
            unsigned int ah[2][4], al[2][4], bh[2][4], bl[2][4];
#pragma unroll
            for (int mi = 0; mi < 2; mi++) {
                LDSM4(ah[mi][0], ah[mi][1], ah[mi][2], ah[mi][3], a_base[mi] + koff);
                LDSM4(al[mi][0], al[mi][1], al[mi][2], al[mi][3], a_base[mi] + koff + A_LO);
            }
#pragma unroll
            for (int nj = 0; nj < 2; nj++) {
                LDSM4(bh[nj][0], bh[nj][1], bh[nj][2], bh[nj][3], b_base[nj] + koff);
                LDSM4(bl[nj][0], bl[nj][1], bl[nj][2], bl[nj][3], b_base[nj] + koff + B_LO);
            }
#pragma unroll
            for (int mi = 0; mi < 2; mi++)
#pragma unroll
                for (int ni = 0; ni < 4; ni++) {
                    const int nj = ni >> 1, of = (ni & 1) * 2;
                    MMA16816(acc[mi][ni], ah[mi][0], ah[mi][1], ah[mi][2], ah[mi][3],
                             bh[nj][of], bh[nj][of + 1]);
                    MMA16816(acc[mi][ni], ah[mi][0], ah[mi][1], ah[mi][2], ah[mi][3],
                             bl[nj][of], bl[nj][of + 1]);
                    MMA16816(acc[mi][ni], al[mi][0], al[mi][1], al[mi][2], al[mi][3],
                             bh[nj][of], bh[nj][of + 1]);
                }
        }
        __syncthreads();
    }

    // ---- epilogue ----
    const int tr = lane >> 2, tc = (lane & 3) * 2;
#pragma unroll
    for (int mi = 0; mi < 2; mi++) {
        const int m = wm * 32 + mi * 16 + tr;
#pragma unroll
        for (int ni = 0; ni < 4; ni++) {
            const int n = n0 + wn * 32 + ni * 8 + tc;
            float2 r0 = {acc[mi][ni][0], acc[mi][ni][1]};
            float2 r1 = {acc[mi][ni][2], acc[mi][ni][3]};
            *(float2*)&C[(size_t)m * p.ldc + n]       = r0;
            *(float2*)&C[(size_t)(m + 8) * p.ldc + n] = r1;
        }
    }
}

// ---------------- RMSNorm ----------------
__global__ __launch_bounds__(256) void rmsnorm_kernel(
    const float* __restrict__ x, const float* __restrict__ g, float* __restrict__ out)
{
    int row = blockIdx.x, tid = threadIdx.x;
    const float4* xr = (const float4*)(x + (size_t)row * DD);
    const float4* gr = (const float4*)g;
    float4 v[4];
    float ss = 0.f;
#pragma unroll
    for (int i = 0; i < 4; i++) {
        v[i] = xr[tid + 256 * i];
        ss += v[i].x * v[i].x + v[i].y * v[i].y + v[i].z * v[i].z + v[i].w * v[i].w;
    }
#pragma unroll
    for (int o = 16; o; o >>= 1) ss += __shfl_xor_sync(0xffffffffu, ss, o);
    __shared__ float sred[8];
    if ((tid & 31) == 0) sred[tid >> 5] = ss;
    __syncthreads();
    float tot = 0.f;
#pragma unroll
    for (int i = 0; i < 8; i++) tot += sred[i];
    float inv = rsqrtf(tot / (float)DD + 1e-5f);
    float4* orow = (float4*)(out + (size_t)row * DD);
#pragma unroll
    for (int i = 0; i < 4; i++) {
        float4 gv = gr[tid + 256 * i];
        float4 o4;
        o4.x = v[i].x * inv * gv.x;
        o4.y = v[i].y * inv * gv.y;
        o4.z = v[i].z * inv * gv.z;
        o4.w = v[i].w * inv * gv.w;
        orow[tid + 256 * i] = o4;
    }
}

// ---------------- paged flash-decode attention ----------------
__global__ __launch_bounds__(128) void attention_kernel(
    const float* __restrict__ kheap, const float* __restrict__ vheap,
    const int*   __restrict__ btab,  const int*  __restrict__ clens,
    const float* __restrict__ scale_p)
{
    int hh = blockIdx.x, b = blockIdx.y;
    int tid = threadIdx.x, lane = tid & 31, w = tid >> 5;
    int ctx = clens[b];
    float scale = scale_p[0];

    const float4* q4 = (const float4*)(g_q + (size_t)b * DD + hh * HDIM);
    float4 qv = q4[lane];

    float m = -1e30f, l = 0.f;
    float4 acc = {0.f, 0.f, 0.f, 0.f};
    const int last = ctx - 1;

    for (int s = w; s < ctx; s += 4) {
        const float *kp, *vp;
        if (s == last) {
            kp = g_k + (size_t)b * DD + hh * HDIM;
            vp = g_v + (size_t)b * DD + hh * HDIM;
        } else {
            int blk = btab[b * MBSN + (s >> 4)];
            size_t base = (((size_t)blk * HH + hh) * PBS + (s & 15)) * HDIM;
            kp = kheap + base;
            vp = vheap + base;
        }
        float4 kv = *(const float4*)(kp + lane * 4);
        float sc = qv.x * kv.x + qv.y * kv.y + qv.z * kv.z + qv.w * kv.w;
#pragma unroll
        for (int o = 16; o; o >>= 1) sc += __shfl_xor_sync(0xffffffffu, sc, o);
        sc *= scale;
        float mn   = fmaxf(m, sc);
        float corr = expf(m - mn);
        float pw   = expf(sc - mn);
        l = l * corr + pw;
        float4 vv = *(const float4*)(vp + lane * 4);
        acc.x = fmaf(pw, vv.x, acc.x * corr);
        acc.y = fmaf(pw, vv.y, acc.y * corr);
        acc.z = fmaf(pw, vv.z, acc.z * corr);
        acc.w = fmaf(pw, vv.w, acc.w * corr);
        m = mn;
    }

    __shared__ float sm_m[4], sm_l[4];
    __shared__ float sm_acc[4][HDIM];
    if (lane == 0) { sm_m[w] = m; sm_l[w] = l; }
    ((float4*)sm_acc[w])[lane] = acc;
    __syncthreads();

    int d = tid;
    float M = fmaxf(fmaxf(sm_m[0], sm_m[1]), fmaxf(sm_m[2], sm_m[3]));
    float L = 0.f, O = 0.f;
#pragma unroll
    for (int i = 0; i < 4; i++) {
        float e = expf(sm_m[i] - M);
        L += sm_l[i] * e;
        O += sm_acc[i][d] * e;
    }
    g_att[(size_t)b * DD + hh * HDIM + d] = O / L;
}

// ---------------- x2 = p0+p1+p2+p3+resid ; h2 = rmsnorm(x2)*g ----------------
__global__ __launch_bounds__(256) void addreduce_rms_kernel(
    const float* __restrict__ resid, const float* __restrict__ g,
    float* __restrict__ xout, float* __restrict__ hout)
{
    int row = blockIdx.x, tid = threadIdx.x;
    const float4* a4 = (const float4*)(g_p0 + (size_t)row * DD);
    const float4* b4 = (const float4*)(g_p1 + (size_t)row * DD);
    const float4* c4 = (const float4*)(g_p2 + (size_t)row * DD);
    const float4* d4 = (const float4*)(g_p3 + (size_t)row * DD);
    const float4* r4 = (const float4*)(resid + (size_t)row * DD);
    const float4* gr = (const float4*)g;
    float4 v[4];
    float ss = 0.f;
#pragma unroll
    for (int i = 0; i < 4; i++) {
        int idx = tid + 256 * i;
        float4 a = a4[idx], b = b4[idx], c = c4[idx], d = d4[idx], r = r4[idx];
        v[i].x = a.x + b.x + c.x + d.x + r.x;
        v[i].y = a.y + b.y + c.y + d.y + r.y;
        v[i].z = a.z + b.z + c.z + d.z + r.z;
        v[i].w = a.w + b.w + c.w + d.w + r.w;
        ss += v[i].x * v[i].x + v[i].y * v[i].y + v[i].z * v[i].z + v[i].w * v[i].w;
    }
#pragma unroll
    for (int o = 16; o; o >>= 1) ss += __shfl_xor_sync(0xffffffffu, ss, o);
    __shared__ float sred[8];
    if ((tid & 31) == 0) sred[tid >> 5] = ss;
    __syncthreads();
    float tot = 0.f;
#pragma unroll
    for (int i = 0; i < 8; i++) tot += sred[i];
    float inv = rsqrtf(tot / (float)DD + 1e-5f);
    float4* xo = (float4*)(xout + (size_t)row * DD);
    float4* ho = (float4*)(hout + (size_t)row * DD);
#pragma unroll
    for (int i = 0; i < 4; i++) {
        int idx = tid + 256 * i;
        xo[idx] = v[i];
        float4 gv = gr[idx];
        float4 o4;
        o4.x = v[i].x * inv * gv.x;
        o4.y = v[i].y * inv * gv.y;
        o4.z = v[i].z * inv * gv.z;
        o4.w = v[i].w * inv * gv.w;
        ho[idx] = o4;
    }
}

// ---------------- gate = silu(ff1) * ff3 ----------------
__global__ __launch_bounds__(256) void silu_mul_kernel()
{
    int idx = blockIdx.x * 256 + threadIdx.x;
    float4 a = ((const float4*)g_ff1)[idx];
    float4 c = ((const float4*)g_ff3)[idx];
    float4 o;
    o.x = a.x / (1.f + expf(-a.x)) * c.x;
    o.y = a.y / (1.f + expf(-a.y)) * c.y;
    o.z = a.z / (1.f + expf(-a.z)) * c.z;
    o.w = a.w / (1.f + expf(-a.w)) * c.w;
    ((float4*)g_gate)[idx] = o;
}

// ---------------- out = p0+p1+p2+p3 + resid ----------------
__global__ __launch_bounds__(256) void final_add_kernel(
    const float* __restrict__ resid, float* __restrict__ out)
{
    int idx = blockIdx.x * 256 + threadIdx.x;
    float4 a = ((const float4*)g_p0)[idx];
    float4 b = ((const float4*)g_p1)[idx];
    float4 c = ((const float4*)g_p2)[idx];
    float4 d = ((const float4*)g_p3)[idx];
    float4 r = ((const float4*)resid)[idx];
    float4 o;
    o.x = a.x + b.x + c.x + d.x + r.x;
    o.y = a.y + b.y + c.y + d.y + r.y;
    o.z = a.z + b.z + c.z + d.z + r.z;
    o.w = a.w + b.w + c.w + d.w + r.w;
    ((float4*)out)[idx] = o;
}

// ---------------- host driver ----------------
extern "C" void kernel_launch(void* const* d_in, const int* in_sizes, int n_in,
                              void* d_out, int out_size)
{
    const float* x     = (const float*)d_in[0];
    const float* kheap = (const float*)d_in[1];
    const float* vheap = (const float*)d_in[2];
    const int*   btab  = (const int*)d_in[3];
    const int*   clens = (const int*)d_in[5];
    const float* scale = (const float*)d_in[9];
    const float* Wq    = (const float*)d_in[13];
    const float* Wk    = (const float*)d_in[14];
    const float* Wv    = (const float*)d_in[15];
    const float* Wo    = (const float*)d_in[16];
    const float* W1    = (const float*)d_in[17];
    const float* W2    = (const float*)d_in[18];
    const float* W3    = (const float*)d_in[19];
    const float* g1    = (const float*)d_in[20];
    const float* g2    = (const float*)d_in[21];
    float* out = (float*)d_out;

    float *h, *q, *k, *v, *att, *x2, *h2, *p0, *p1, *p2, *p3, *ff1, *ff3, *gate;
    cudaGetSymbolAddress((void**)&h,   g_h);
    cudaGetSymbolAddress((void**)&q,   g_q);
    cudaGetSymbolAddress((void**)&k,   g_k);
    cudaGetSymbolAddress((void**)&v,   g_v);
    cudaGetSymbolAddress((void**)&att, g_att);
    cudaGetSymbolAddress((void**)&x2,  g_x2);
    cudaGetSymbolAddress((void**)&h2,  g_h2);
    cudaGetSymbolAddress((void**)&p0,  g_p0);
    cudaGetSymbolAddress((void**)&p1,  g_p1);
    cudaGetSymbolAddress((void**)&p2,  g_p2);
    cudaGetSymbolAddress((void**)&p3,  g_p3);
    cudaGetSymbolAddress((void**)&ff1, g_ff1);
    cudaGetSymbolAddress((void**)&ff3, g_ff3);
    cudaGetSymbolAddress((void**)&gate, g_gate);

    const int SMEM = (2 * 64 * KPAD + 2 * 128 * KPAD) * 2;  // bytes
    cudaFuncSetAttribute(bf16gemm_kernel,
                         cudaFuncAttributeMaxDynamicSharedMemorySize, SMEM);

    // 1) h = rmsnorm(x) * g1
    rmsnorm_kernel<<<BB, 256>>>(x, g1, h);

    // 2) q,k,v = h @ {Wq,Wk,Wv}^T
    {
        GP p;
        p.A = h; p.lda = DD; p.ldc = DD; p.nbpj = DD / 128;
        p.jobs[0] = {Wq, q, 0, DD};
        p.jobs[1] = {Wk, k, 0, DD};
        p.jobs[2] = {Wv, v, 0, DD};
        p.jobs[3] = {Wq, q, 0, 0};
        bf16gemm_kernel<<<3 * (DD / 128), 256, SMEM>>>(p);
    }

    // 3) paged attention
    attention_kernel<<<dim3(HH, BB), 128>>>(kheap, vheap, btab, clens, scale);

    // 4) att @ Wo^T, split-K=4 -> p0..p3
    {
        GP p;
        p.A = att; p.lda = DD; p.ldc = DD; p.nbpj = DD / 128;
        p.jobs[0] = {Wo, p0, 0 * (DD / 4), 1 * (DD / 4)};
        p.jobs[1] = {Wo, p1, 1 * (DD / 4), 2 * (DD / 4)};
        p.jobs[2] = {Wo, p2, 2 * (DD / 4), 3 * (DD / 4)};
        p.jobs[3] = {Wo, p3, 3 * (DD / 4), 4 * (DD / 4)};
        bf16gemm_kernel<<<4 * (DD / 128), 256, SMEM>>>(p);
    }

    // 5) x2 = sum(p)+x ; h2 = rmsnorm(x2) * g2
    addreduce_rms_kernel<<<BB, 256>>>(x, g2, x2, h2);

    // 6) ff1 = h2 @ W1^T, ff3 = h2 @ W3^T
    {
        GP p;
        p.A = h2; p.lda = DD; p.ldc = DFF; p.nbpj = DFF / 128;
        p.jobs[0] = {W1, ff1, 0, DD};
        p.jobs[1] = {W3, ff3, 0, DD};
        p.jobs[2] = {W1, ff1, 0, 0};
        p.jobs[3] = {W1, ff1, 0, 0};
        bf16gemm_kernel<<<2 * (DFF / 128), 256, SMEM>>>(p);
    }

    // 7) gate = silu(ff1) * ff3
    silu_mul_kernel<<<(BB * DFF) / 4 / 256, 256>>>();

    // 8) gate @ W2^T, split-K=4 -> p0..p3
    {
        GP p;
        p.A = gate; p.lda = DFF; p.ldc = DD; p.nbpj = DD / 128;
        p.jobs[0] = {W2, p0, 0 * (DFF / 4), 1 * (DFF / 4)};
        p.jobs[1] = {W2, p1, 1 * (DFF / 4), 2 * (DFF / 4)};
        p.jobs[2] = {W2, p2, 2 * (DFF / 4), 3 * (DFF / 4)};
        p.jobs[3] = {W2, p3, 3 * (DFF / 4), 4 * (DFF / 4)};
        bf16gemm_kernel<<<4 * (DD / 128), 256, SMEM>>>(p);
    }

    // 9) out = sum(p) + x2
    final_add_kernel<<<(BB * DD) / 4 / 256, 256>>>(x2, out);
}

// round 5
// speedup vs baseline: 1.9788x; 1.1456x over previous
#include <cuda_runtime.h>
#include <cuda_bf16.h>
#include <math.h>
#include <stdint.h>

#define BB   64
#define DD   4096
#define HH   32
#define HDIM 128
#define PBS  16
#define MBSN 32
#define DFF  16384

// ---------------- device scratch ----------------
__device__ float g_h  [BB * DD];
__device__ float g_q  [BB * DD];
__device__ float g_k  [BB * DD];
__device__ float g_v  [BB * DD];
__device__ float g_att[BB * DD];
__device__ float g_x2 [BB * DD];
__device__ float g_h2 [BB * DD];
__device__ float g_p0 [BB * DD];
__device__ float g_p1 [BB * DD];
__device__ float g_p2 [BB * DD];
__device__ float g_p3 [BB * DD];
__device__ float g_ff1[BB * DFF];
__device__ float g_ff3[BB * DFF];
__device__ float g_gate[BB * DFF];

// ---------------- PTX helpers ----------------
#define LDSM4(r0, r1, r2, r3, addr)                                          \
    asm volatile("ldmatrix.sync.aligned.m8n8.x4.shared.b16 {%0,%1,%2,%3}, [%4];" \
                 : "=r"(r0), "=r"(r1), "=r"(r2), "=r"(r3) : "r"(addr))

#define MMA16816(d, a0, a1, a2, a3, b0, b1)                                   \
    asm volatile("mma.sync.aligned.m16n8k16.row.col.f32.bf16.bf16.f32 "       \
                 "{%0,%1,%2,%3},{%4,%5,%6,%7},{%8,%9},{%0,%1,%2,%3};"         \
                 : "+f"(d[0]), "+f"(d[1]), "+f"(d[2]), "+f"(d[3])             \
                 : "r"(a0), "r"(a1), "r"(a2), "r"(a3), "r"(b0), "r"(b1))

// split fp32 -> (hi, lo) bf16 and pack 4 consecutive into uint2 each
__device__ __forceinline__ void cvt_split4(float4 v, uint2& uh, uint2& ul)
{
    __nv_bfloat16 h0 = __float2bfloat16_rn(v.x);
    __nv_bfloat16 h1 = __float2bfloat16_rn(v.y);
    __nv_bfloat16 h2 = __float2bfloat16_rn(v.z);
    __nv_bfloat16 h3 = __float2bfloat16_rn(v.w);
    __nv_bfloat16 l0 = __float2bfloat16_rn(v.x - __bfloat162float(h0));
    __nv_bfloat16 l1 = __float2bfloat16_rn(v.y - __bfloat162float(h1));
    __nv_bfloat16 l2 = __float2bfloat16_rn(v.z - __bfloat162float(h2));
    __nv_bfloat16 l3 = __float2bfloat16_rn(v.w - __bfloat162float(h3));
    __nv_bfloat162 ph01 = __halves2bfloat162(h0, h1);
    __nv_bfloat162 ph23 = __halves2bfloat162(h2, h3);
    __nv_bfloat162 pl01 = __halves2bfloat162(l0, l1);
    __nv_bfloat162 pl23 = __halves2bfloat162(l2, l3);
    uh.x = *(unsigned int*)&ph01; uh.y = *(unsigned int*)&ph23;
    ul.x = *(unsigned int*)&pl01; ul.y = *(unsigned int*)&pl23;
}

// ---------------- bf16-split tensor-core GEMM (2-stage pipelined) --------
// C[64, N] = A[64, K] @ W[N, K]^T. Tile M=64, N=128, Kc=64. 8 warps (2Mx4N).
struct Job { const float* W; float* C; int k0, k1; };
struct GP  { const float* A; int lda; int ldc; int nbpj; Job jobs[4]; };

#define KPAD 72
#define ST_ELE (2 * 64 * KPAD + 2 * 128 * KPAD)   // bf16 elems per stage
#define STAGE_BYTES (ST_ELE * 2)

__global__ __launch_bounds__(256) void bf16gemm_kernel(GP p)
{
    int job = blockIdx.x / p.nbpj;
    int nb  = blockIdx.x % p.nbpj;
    const float* W = p.jobs[job].W;
    float*       C = p.jobs[job].C;
    const int k0j = p.jobs[job].k0, k1j = p.jobs[job].k1;
    const int n0  = nb * 128;

    extern __shared__ __nv_bfloat16 smem_bf[];

    const int tid = threadIdx.x, lane = tid & 31, w = tid >> 5;
    const int wm = w & 1, wn = w >> 1;

    const int arow = (lane & 7) + (lane & 8);
    const int acol = (lane & 16) >> 1;
    const int brow = (lane & 7) + ((lane & 16) >> 1);
    const int bcol = lane & 8;

    float acc[2][4][4];
#pragma unroll
    for (int i = 0; i < 2; i++)
#pragma unroll
        for (int j = 0; j < 4; j++)
#pragma unroll
            for (int t = 0; t < 4; t++) acc[i][j][t] = 0.f;

    const int lrowA = tid >> 2, lcolA = (tid & 3) * 16;
    const int lrowW = tid >> 1, lcolW = (tid & 1) * 32;
    const float* Arow = p.A + (size_t)lrowA * p.lda + lcolA;
    const float* Wrow = W + (size_t)(n0 + lrowW) * p.lda + lcolW;

    // stage-0 conversion-store pointers
    __nv_bfloat16* sa_h0 = smem_bf + lrowA * KPAD + lcolA;
    __nv_bfloat16* sa_l0 = sa_h0 + 64 * KPAD;
    __nv_bfloat16* sb_h0 = smem_bf + 2 * 64 * KPAD + lrowW * KPAD + lcolW;
    __nv_bfloat16* sb_l0 = sb_h0 + 128 * KPAD;

    // stage-0 ldmatrix bases
    unsigned int a_base[2], b_base[2];
#pragma unroll
    for (int mi = 0; mi < 2; mi++)
        a_base[mi] = (unsigned int)__cvta_generic_to_shared(
            smem_bf + (wm * 32 + mi * 16 + arow) * KPAD + acol);
#pragma unroll
    for (int nj = 0; nj < 2; nj++)
        b_base[nj] = (unsigned int)__cvta_generic_to_shared(
            smem_bf + 2 * 64 * KPAD + (wn * 32 + nj * 16 + brow) * KPAD + bcol);
    const unsigned int A_LO = 64 * KPAD * 2;    // bytes
    const unsigned int B_LO = 128 * KPAD * 2;

    const int nch = (k1j - k0j) >> 6;

    // ---- prefetch chunk 0 into registers ----
    float4 ra[4], rw[8];
#pragma unroll
    for (int i = 0; i < 4; i++) ra[i] = *(const float4*)(Arow + k0j + 4 * i);
#pragma unroll
    for (int i = 0; i < 8; i++) rw[i] = *(const float4*)(Wrow + k0j + 4 * i);

    // ---- convert chunk 0 into stage 0 ----
#pragma unroll
    for (int i = 0; i < 4; i++) {
        uint2 uh, ul;
        cvt_split4(ra[i], uh, ul);
        *(uint2*)(sa_h0 + 4 * i) = uh;
        *(uint2*)(sa_l0 + 4 * i) = ul;
    }
#pragma unroll
    for (int i = 0; i < 8; i++) {
        uint2 uh, ul;
        cvt_split4(rw[i], uh, ul);
        *(uint2*)(sb_h0 + 4 * i) = uh;
        *(uint2*)(sb_l0 + 4 * i) = ul;
    }
    __syncthreads();

    for (int c = 0; c < nch; c++) {
        const bool more = (c + 1) < nch;
        // ---- issue next-chunk LDGs (latency overlapped by MMAs below) ----
        if (more) {
            const int kn = k0j + (c + 1) * 64;
#pragma unroll
            for (int i = 0; i < 4; i++) ra[i] = *(const float4*)(Arow + kn + 4 * i);
#pragma unroll
            for (int i = 0; i < 8; i++) rw[i] = *(const float4*)(Wrow + kn + 4 * i);
        }

        // ---- MMAs on stage (c&1) ----
        const unsigned int sb_off = (unsigned int)(c & 1) * STAGE_BYTES;
#pragma unroll
        for (int ks = 0; ks < 4; ks++) {
            const unsigned int koff = sb_off + ks * 16 * 2;
            unsigned int ah[2][4], al[2][4], bh[2][4], bl[2][4];
#pragma unroll
            for (int mi = 0; mi < 2; mi++) {
                LDSM4(ah[mi][0], ah[mi][1], ah[mi][2], ah[mi][3], a_base[mi] + koff);
                LDSM4(al[mi][0], al[mi][1], al[mi][2], al[mi][3], a_base[mi] + koff + A_LO);
            }
#pragma unroll
            for (int nj = 0; nj < 2; nj++) {
                LDSM4(bh[nj][0], bh[nj][1], bh[nj][2], bh[nj][3], b_base[nj] + koff);
                LDSM4(bl[nj][0], bl[nj][1], bl[nj][2], bl[nj][3], b_base[nj] + koff + B_LO);
            }
#pragma unroll
            for (int mi = 0; mi < 2; mi++)
#pragma unroll
                for (int ni = 0; ni < 4; ni++) {
                    const int nj = ni >> 1, of = (ni & 1) * 2;
                    MMA16816(acc[mi][ni], ah[mi][0], ah[mi][1], ah[mi][2], ah[mi][3],
                             bh[nj][of], bh[nj][of + 1]);
                    MMA16816(acc[mi][ni], ah[mi][0], ah[mi][1], ah[mi][2], ah[mi][3],
                             bl[nj][of], bl[nj][of + 1]);
                    MMA16816(acc[mi][ni], al[mi][0], al[mi][1], al[mi][2], al[mi][3],
                             bh[nj][of], bh[nj][of + 1]);
                }
        }

        // ---- convert prefetched regs into the other stage ----
        if (more) {
            const int st = ((c + 1) & 1) * ST_ELE;
#pragma unroll
            for (int i = 0; i < 4; i++) {
                uint2 uh, ul;
                cvt_split4(ra[i], uh, ul);
                *(uint2*)(sa_h0 + st + 4 * i) = uh;
                *(uint2*)(sa_l0 + st + 4 * i) = ul;
            }
#pragma unroll
            for (int i = 0; i < 8; i++) {
                uint2 uh, ul;
                cvt_split4(rw[i], uh, ul);
                *(uint2*)(sb_h0 + st + 4 * i) = uh;
                *(uint2*)(sb_l0 + st + 4 * i) = ul;
            }
        }
        __syncthreads();
    }

    // ---- epilogue ----
    const int tr = lane >> 2, tc = (lane & 3) * 2;
#pragma unroll
    for (int mi = 0; mi < 2; mi++) {
        const int m = wm * 32 + mi * 16 + tr;
#pragma unroll
        for (int ni = 0; ni < 4; ni++) {
            const int n = n0 + wn * 32 + ni * 8 + tc;
            float2 r0 = {acc[mi][ni][0], acc[mi][ni][1]};
            float2 r1 = {acc[mi][ni][2], acc[mi][ni][3]};
            *(float2*)&C[(size_t)m * p.ldc + n]       = r0;
            *(float2*)&C[(size_t)(m + 8) * p.ldc + n] = r1;
        }
    }
}

// ---------------- RMSNorm ----------------
__global__ __launch_bounds__(256) void rmsnorm_kernel(
    const float* __restrict__ x, const float* __restrict__ g, float* __restrict__ out)
{
    int row = blockIdx.x, tid = threadIdx.x;
    const float4* xr = (const float4*)(x + (size_t)row * DD);
    const float4* gr = (const float4*)g;
    float4 v[4];
    float ss = 0.f;
#pragma unroll
    for (int i = 0; i < 4; i++) {
        v[i] = xr[tid + 256 * i];
        ss += v[i].x * v[i].x + v[i].y * v[i].y + v[i].z * v[i].z + v[i].w * v[i].w;
    }
#pragma unroll
    for (int o = 16; o; o >>= 1) ss += __shfl_xor_sync(0xffffffffu, ss, o);
    __shared__ float sred[8];
    if ((tid & 31) == 0) sred[tid >> 5] = ss;
    __syncthreads();
    float tot = 0.f;
#pragma unroll
    for (int i = 0; i < 8; i++) tot += sred[i];
    float inv = rsqrtf(tot / (float)DD + 1e-5f);
    float4* orow = (float4*)(out + (size_t)row * DD);
#pragma unroll
    for (int i = 0; i < 4; i++) {
        float4 gv = gr[tid + 256 * i];
        float4 o4;
        o4.x = v[i].x * inv * gv.x;
        o4.y = v[i].y * inv * gv.y;
        o4.z = v[i].z * inv * gv.z;
        o4.w = v[i].w * inv * gv.w;
        orow[tid + 256 * i] = o4;
    }
}

// ---------------- paged flash-decode attention (8 warps) ----------------
__global__ __launch_bounds__(256) void attention_kernel(
    const float* __restrict__ kheap, const float* __restrict__ vheap,
    const int*   __restrict__ btab,  const int*  __restrict__ clens,
    const float* __restrict__ scale_p)
{
    int hh = blockIdx.x, b = blockIdx.y;
    int tid = threadIdx.x, lane = tid & 31, w = tid >> 5;
    int ctx = clens[b];
    float scale = scale_p[0];

    const float4* q4 = (const float4*)(g_q + (size_t)b * DD + hh * HDIM);
    float4 qv = q4[lane];

    float m = -1e30f, l = 0.f;
    float4 acc = {0.f, 0.f, 0.f, 0.f};
    const int last = ctx - 1;

    for (int s = w; s < ctx; s += 8) {
        const float *kp, *vp;
        if (s == last) {
            kp = g_k + (size_t)b * DD + hh * HDIM;
            vp = g_v + (size_t)b * DD + hh * HDIM;
        } else {
            int blk = btab[b * MBSN + (s >> 4)];
            size_t base = (((size_t)blk * HH + hh) * PBS + (s & 15)) * HDIM;
            kp = kheap + base;
            vp = vheap + base;
        }
        float4 kv = *(const float4*)(kp + lane * 4);
        float sc = qv.x * kv.x + qv.y * kv.y + qv.z * kv.z + qv.w * kv.w;
#pragma unroll
        for (int o = 16; o; o >>= 1) sc += __shfl_xor_sync(0xffffffffu, sc, o);
        sc *= scale;
        float mn   = fmaxf(m, sc);
        float corr = expf(m - mn);
        float pw   = expf(sc - mn);
        l = l * corr + pw;
        float4 vv = *(const float4*)(vp + lane * 4);
        acc.x = fmaf(pw, vv.x, acc.x * corr);
        acc.y = fmaf(pw, vv.y, acc.y * corr);
        acc.z = fmaf(pw, vv.z, acc.z * corr);
        acc.w = fmaf(pw, vv.w, acc.w * corr);
        m = mn;
    }

    __shared__ float sm_m[8], sm_l[8];
    __shared__ float sm_acc[8][HDIM];
    if (lane == 0) { sm_m[w] = m; sm_l[w] = l; }
    ((float4*)sm_acc[w])[lane] = acc;
    __syncthreads();

    if (tid < HDIM) {
        int d = tid;
        float M = -1e30f;
#pragma unroll
        for (int i = 0; i < 8; i++) M = fmaxf(M, sm_m[i]);
        float L = 0.f, O = 0.f;
#pragma unroll
        for (int i = 0; i < 8; i++) {
            float e = expf(sm_m[i] - M);
            L += sm_l[i] * e;
            O += sm_acc[i][d] * e;
        }
        g_att[(size_t)b * DD + hh * HDIM + d] = O / L;
    }
}

// ---------------- x2 = p0+p1+p2+p3+resid ; h2 = rmsnorm(x2)*g ----------------
__global__ __launch_bounds__(256) void addreduce_rms_kernel(
    const float* __restrict__ resid, const float* __restrict__ g,
    float* __restrict__ xout, float* __restrict__ hout)
{
    int row = blockIdx.x, tid = threadIdx.x;
    const float4* a4 = (const float4*)(g_p0 + (size_t)row * DD);
    const float4* b4 = (const float4*)(g_p1 + (size_t)row * DD);
    const float4* c4 = (const float4*)(g_p2 + (size_t)row * DD);
    const float4* d4 = (const float4*)(g_p3 + (size_t)row * DD);
    const float4* r4 = (const float4*)(resid + (size_t)row * DD);
    const float4* gr = (const float4*)g;
    float4 v[4];
    float ss = 0.f;
#pragma unroll
    for (int i = 0; i < 4; i++) {
        int idx = tid + 256 * i;
        float4 a = a4[idx], b = b4[idx], c = c4[idx], d = d4[idx], r = r4[idx];
        v[i].x = a.x + b.x + c.x + d.x + r.x;
        v[i].y = a.y + b.y + c.y + d.y + r.y;
        v[i].z = a.z + b.z + c.z + d.z + r.z;
        v[i].w = a.w + b.w + c.w + d.w + r.w;
        ss += v[i].x * v[i].x + v[i].y * v[i].y + v[i].z * v[i].z + v[i].w * v[i].w;
    }
#pragma unroll
    for (int o = 16; o; o >>= 1) ss += __shfl_xor_sync(0xffffffffu, ss, o);
    __shared__ float sred[8];
    if ((tid & 31) == 0) sred[tid >> 5] = ss;
    __syncthreads();
    float tot = 0.f;
#pragma unroll
    for (int i = 0; i < 8; i++) tot += sred[i];
    float inv = rsqrtf(tot / (float)DD + 1e-5f);
    float4* xo = (float4*)(xout + (size_t)row * DD);
    float4* ho = (float4*)(hout + (size_t)row * DD);
#pragma unroll
    for (int i = 0; i < 4; i++) {
        int idx = tid + 256 * i;
        xo[idx] = v[i];
        float4 gv = gr[idx];
        float4 o4;
        o4.x = v[i].x * inv * gv.x;
        o4.y = v[i].y * inv * gv.y;
        o4.z = v[i].z * inv * gv.z;
        o4.w = v[i].w * inv * gv.w;
        ho[idx] = o4;
    }
}

// ---------------- gate = silu(ff1) * ff3 ----------------
__global__ __launch_bounds__(256) void silu_mul_kernel()
{
    int idx = blockIdx.x * 256 + threadIdx.x;
    float4 a = ((const float4*)g_ff1)[idx];
    float4 c = ((const float4*)g_ff3)[idx];
    float4 o;
    o.x = a.x / (1.f + expf(-a.x)) * c.x;
    o.y = a.y / (1.f + expf(-a.y)) * c.y;
    o.z = a.z / (1.f + expf(-a.z)) * c.z;
    o.w = a.w / (1.f + expf(-a.w)) * c.w;
    ((float4*)g_gate)[idx] = o;
}

// ---------------- out = p0+p1+p2+p3 + resid ----------------
__global__ __launch_bounds__(256) void final_add_kernel(
    const float* __restrict__ resid, float* __restrict__ out)
{
    int idx = blockIdx.x * 256 + threadIdx.x;
    float4 a = ((const float4*)g_p0)[idx];
    float4 b = ((const float4*)g_p1)[idx];
    float4 c = ((const float4*)g_p2)[idx];
    float4 d = ((const float4*)g_p3)[idx];
    float4 r = ((const float4*)resid)[idx];
    float4 o;
    o.x = a.x + b.x + c.x + d.x + r.x;
    o.y = a.y + b.y + c.y + d.y + r.y;
    o.z = a.z + b.z + c.z + d.z + r.z;
    o.w = a.w + b.w + c.w + d.w + r.w;
    ((float4*)out)[idx] = o;
}

// ---------------- host driver ----------------
extern "C" void kernel_launch(void* const* d_in, const int* in_sizes, int n_in,
                              void* d_out, int out_size)
{
    const float* x     = (const float*)d_in[0];
    const float* kheap = (const float*)d_in[1];
    const float* vheap = (const float*)d_in[2];
    const int*   btab  = (const int*)d_in[3];
    const int*   clens = (const int*)d_in[5];
    const float* scale = (const float*)d_in[9];
    const float* Wq    = (const float*)d_in[13];
    const float* Wk    = (const float*)d_in[14];
    const float* Wv    = (const float*)d_in[15];
    const float* Wo    = (const float*)d_in[16];
    const float* W1    = (const float*)d_in[17];
    const float* W2    = (const float*)d_in[18];
    const float* W3    = (const float*)d_in[19];
    const float* g1    = (const float*)d_in[20];
    const float* g2    = (const float*)d_in[21];
    float* out = (float*)d_out;

    float *h, *q, *k, *v, *att, *x2, *h2, *p0, *p1, *p2, *p3, *ff1, *ff3, *gate;
    cudaGetSymbolAddress((void**)&h,   g_h);
    cudaGetSymbolAddress((void**)&q,   g_q);
    cudaGetSymbolAddress((void**)&k,   g_k);
    cudaGetSymbolAddress((void**)&v,   g_v);
    cudaGetSymbolAddress((void**)&att, g_att);
    cudaGetSymbolAddress((void**)&x2,  g_x2);
    cudaGetSymbolAddress((void**)&h2,  g_h2);
    cudaGetSymbolAddress((void**)&p0,  g_p0);
    cudaGetSymbolAddress((void**)&p1,  g_p1);
    cudaGetSymbolAddress((void**)&p2,  g_p2);
    cudaGetSymbolAddress((void**)&p3,  g_p3);
    cudaGetSymbolAddress((void**)&ff1, g_ff1);
    cudaGetSymbolAddress((void**)&ff3, g_ff3);
    cudaGetSymbolAddress((void**)&gate, g_gate);

    const int SMEM = 2 * STAGE_BYTES;   // two stages
    cudaFuncSetAttribute(bf16gemm_kernel,
                         cudaFuncAttributeMaxDynamicSharedMemorySize, SMEM);

    // 1) h = rmsnorm(x) * g1
    rmsnorm_kernel<<<BB, 256>>>(x, g1, h);

    // 2) q,k,v = h @ {Wq,Wk,Wv}^T
    {
        GP p;
        p.A = h; p.lda = DD; p.ldc = DD; p.nbpj = DD / 128;
        p.jobs[0] = {Wq, q, 0, DD};
        p.jobs[1] = {Wk, k, 0, DD};
        p.jobs[2] = {Wv, v, 0, DD};
        p.jobs[3] = {Wq, q, 0, 0};
        bf16gemm_kernel<<<3 * (DD / 128), 256, SMEM>>>(p);
    }

    // 3) paged attention
    attention_kernel<<<dim3(HH, BB), 256>>>(kheap, vheap, btab, clens, scale);

    // 4) att @ Wo^T, split-K=4 -> p0..p3
    {
        GP p;
        p.A = att; p.lda = DD; p.ldc = DD; p.nbpj = DD / 128;
        p.jobs[0] = {Wo, p0, 0 * (DD / 4), 1 * (DD / 4)};
        p.jobs[1] = {Wo, p1, 1 * (DD / 4), 2 * (DD / 4)};
        p.jobs[2] = {Wo, p2, 2 * (DD / 4), 3 * (DD / 4)};
        p.jobs[3] = {Wo, p3, 3 * (DD / 4), 4 * (DD / 4)};
        bf16gemm_kernel<<<4 * (DD / 128), 256, SMEM>>>(p);
    }

    // 5) x2 = sum(p)+x ; h2 = rmsnorm(x2) * g2
    addreduce_rms_kernel<<<BB, 256>>>(x, g2, x2, h2);

    // 6) ff1 = h2 @ W1^T, ff3 = h2 @ W3^T
    {
        GP p;
        p.A = h2; p.lda = DD; p.ldc = DFF; p.nbpj = DFF / 128;
        p.jobs[0] = {W1, ff1, 0, DD};
        p.jobs[1] = {W3, ff3, 0, DD};
        p.jobs[2] = {W1, ff1, 0, 0};
        p.jobs[3] = {W1, ff1, 0, 0};
        bf16gemm_kernel<<<2 * (DFF / 128), 256, SMEM>>>(p);
    }

    // 7) gate = silu(ff1) * ff3
    silu_mul_kernel<<<(BB * DFF) / 4 / 256, 256>>>();

    // 8) gate @ W2^T, split-K=4 -> p0..p3
    {
        GP p;
        p.A = gate; p.lda = DFF; p.ldc = DD; p.nbpj = DD / 128;
        p.jobs[0] = {W2, p0, 0 * (DFF / 4), 1 * (DFF / 4)};
        p.jobs[1] = {W2, p1, 1 * (DFF / 4), 2 * (DFF / 4)};
        p.jobs[2] = {W2, p2, 2 * (DFF / 4), 3 * (DFF / 4)};
        p.jobs[3] = {W2, p3, 3 * (DFF / 4), 4 * (DFF / 4)};
        bf16gemm_kernel<<<4 * (DD / 128), 256, SMEM>>>(p);
    }

    // 9) out = sum(p) + x2
    final_add_kernel<<<(BB * DD) / 4 / 256, 256>>>(x2, out);
}

// round 9
// speedup vs baseline: 2.3848x; 1.2052x over previous
#include <cuda_runtime.h>
#include <cuda_bf16.h>
#include <math.h>
#include <stdint.h>

#define BB   64
#define DD   4096
#define HH   32
#define HDIM 128
#define PBS  16
#define MBSN 32
#define DFF  16384

// ---------------- device scratch ----------------
__device__ float g_h  [BB * DD];
__device__ float g_q  [BB * DD];
__device__ float g_k  [BB * DD];
__device__ float g_v  [BB * DD];
__device__ float g_att[BB * DD];
__device__ float g_x2 [BB * DD];
__device__ float g_h2 [BB * DD];
__device__ float g_pt [16][BB * DD];     // split-K partials
__device__ float g_ff1 [BB * DFF];
__device__ float g_ff1b[BB * DFF];
__device__ float g_ff3 [BB * DFF];
__device__ float g_ff3b[BB * DFF];
__device__ float g_gate[BB * DFF];

// ---------------- PTX helpers ----------------
#define LDSM4(r0, r1, r2, r3, addr)                                          \
    asm volatile("ldmatrix.sync.aligned.m8n8.x4.shared.b16 {%0,%1,%2,%3}, [%4];" \
                 : "=r"(r0), "=r"(r1), "=r"(r2), "=r"(r3) : "r"(addr))

#define MMA16816(d, a0, a1, a2, a3, b0, b1)                                   \
    asm volatile("mma.sync.aligned.m16n8k16.row.col.f32.bf16.bf16.f32 "       \
                 "{%0,%1,%2,%3},{%4,%5,%6,%7},{%8,%9},{%0,%1,%2,%3};"         \
                 : "+f"(d[0]), "+f"(d[1]), "+f"(d[2]), "+f"(d[3])             \
                 : "r"(a0), "r"(a1), "r"(a2), "r"(a3), "r"(b0), "r"(b1))

// split fp32 -> (hi, lo) bf16, packed pairs (low instruction count)
__device__ __forceinline__ void cvt_split4(float4 v, uint2& uh, uint2& ul)
{
    __nv_bfloat162 h01 = __floats2bfloat162_rn(v.x, v.y);
    __nv_bfloat162 h23 = __floats2bfloat162_rn(v.z, v.w);
    float lx = v.x - __bfloat162float(__low2bfloat16(h01));
    float ly = v.y - __bfloat162float(__high2bfloat16(h01));
    float lz = v.z - __bfloat162float(__low2bfloat16(h23));
    float lw = v.w - __bfloat162float(__high2bfloat16(h23));
    __nv_bfloat162 l01 = __floats2bfloat162_rn(lx, ly);
    __nv_bfloat162 l23 = __floats2bfloat162_rn(lz, lw);
    uh.x = *(unsigned int*)&h01; uh.y = *(unsigned int*)&h23;
    ul.x = *(unsigned int*)&l01; ul.y = *(unsigned int*)&l23;
}

// ---------------- bf16-split tensor-core GEMM (2-stage pipelined) --------
// C[64, N] = A[64, K] @ W[N, K]^T. Tile M=64, N=128, Kc=64. 8 warps (2Mx4N).
struct Job { const float* W; float* C; int k0, k1; };
struct GP  { const float* A; int lda; int ldc; int nbpj; Job jobs[16]; };

#define KPAD 72
#define ST_ELE (2 * 64 * KPAD + 2 * 128 * KPAD)   // bf16 elems per stage
#define STAGE_BYTES (ST_ELE * 2)

__global__ __launch_bounds__(256, 2) void bf16gemm_kernel(GP p)
{
    int job = blockIdx.x / p.nbpj;
    int nb  = blockIdx.x % p.nbpj;
    const float* W = p.jobs[job].W;
    float*       C = p.jobs[job].C;
    const int k0j = p.jobs[job].k0, k1j = p.jobs[job].k1;
    const int n0  = nb * 128;

    extern __shared__ __nv_bfloat16 smem_bf[];

    const int tid = threadIdx.x, lane = tid & 31, w = tid >> 5;
    const int wm = w & 1, wn = w >> 1;

    const int arow = (lane & 7) + (lane & 8);
    const int acol = (lane & 16) >> 1;
    const int brow = (lane & 7) + ((lane & 16) >> 1);
    const int bcol = lane & 8;

    float acc[2][4][4];
#pragma unroll
    for (int i = 0; i < 2; i++)
#pragma unroll
        for (int j = 0; j < 4; j++)
#pragma unroll
            for (int t = 0; t < 4; t++) acc[i][j][t] = 0.f;

    const int lrowA = tid >> 2, lcolA = (tid & 3) * 16;
    const int lrowW = tid >> 1, lcolW = (tid & 1) * 32;
    const float* Arow = p.A + (size_t)lrowA * p.lda + lcolA;
    const float* Wrow = W + (size_t)(n0 + lrowW) * p.lda + lcolW;

    __nv_bfloat16* sa_h0 = smem_bf + lrowA * KPAD + lcolA;
    __nv_bfloat16* sa_l0 = sa_h0 + 64 * KPAD;
    __nv_bfloat16* sb_h0 = smem_bf + 2 * 64 * KPAD + lrowW * KPAD + lcolW;
    __nv_bfloat16* sb_l0 = sb_h0 + 128 * KPAD;

    unsigned int a_base[2], b_base[2];
#pragma unroll
    for (int mi = 0; mi < 2; mi++)
        a_base[mi] = (unsigned int)__cvta_generic_to_shared(
            smem_bf + (wm * 32 + mi * 16 + arow) * KPAD + acol);
#pragma unroll
    for (int nj = 0; nj < 2; nj++)
        b_base[nj] = (unsigned int)__cvta_generic_to_shared(
            smem_bf + 2 * 64 * KPAD + (wn * 32 + nj * 16 + brow) * KPAD + bcol);
    const unsigned int A_LO = 64 * KPAD * 2;    // bytes
    const unsigned int B_LO = 128 * KPAD * 2;

    const int nch = (k1j - k0j) >> 6;

    // ---- prefetch chunk 0 into registers ----
    float4 ra[4], rw[8];
#pragma unroll
    for (int i = 0; i < 4; i++) ra[i] = *(const float4*)(Arow + k0j + 4 * i);
#pragma unroll
    for (int i = 0; i < 8; i++) rw[i] = *(const float4*)(Wrow + k0j + 4 * i);

    // ---- convert chunk 0 into stage 0 ----
#pragma unroll
    for (int i = 0; i < 4; i++) {
        uint2 uh, ul;
        cvt_split4(ra[i], uh, ul);
        *(uint2*)(sa_h0 + 4 * i) = uh;
        *(uint2*)(sa_l0 + 4 * i) = ul;
    }
#pragma unroll
    for (int i = 0; i < 8; i++) {
        uint2 uh, ul;
        cvt_split4(rw[i], uh, ul);
        *(uint2*)(sb_h0 + 4 * i) = uh;
        *(uint2*)(sb_l0 + 4 * i) = ul;
    }
    __syncthreads();

    for (int c = 0; c < nch; c++) {
        const bool more = (c + 1) < nch;
        if (more) {
            const int kn = k0j + (c + 1) * 64;
#pragma unroll
            for (int i = 0; i < 4; i++) ra[i] = *(const float4*)(Arow + kn + 4 * i);
#pragma unroll
            for (int i = 0; i < 8; i++) rw[i] = *(const float4*)(Wrow + kn + 4 * i);
        }

        const unsigned int sb_off = (unsigned int)(c & 1) * STAGE_BYTES;
#pragma unroll
        for (int ks = 0; ks < 4; ks++) {
            const unsigned int koff = sb_off + ks * 16 * 2;
            unsigned int ah[2][4], al[2][4], bh[2][4], bl[2][4];
#pragma unroll
            for (int mi = 0; mi < 2; mi++) {
                LDSM4(ah[mi][0], ah[mi][1], ah[mi][2], ah[mi][3], a_base[mi] + koff);
                LDSM4(al[mi][0], al[mi][1], al[mi][2], al[mi][3], a_base[mi] + koff + A_LO);
            }
#pragma unroll
            for (int nj = 0; nj < 2; nj++) {
                LDSM4(bh[nj][0], bh[nj][1], bh[nj][2], bh[nj][3], b_base[nj] + koff);
                LDSM4(bl[nj][0], bl[nj][1], bl[nj][2], bl[nj][3], b_base[nj] + koff + B_LO);
            }
#pragma unroll
            for (int mi = 0; mi < 2; mi++)
#pragma unroll
                for (int ni = 0; ni < 4; ni++) {
                    const int nj = ni >> 1, of = (ni & 1) * 2;
                    MMA16816(acc[mi][ni], ah[mi][0], ah[mi][1], ah[mi][2], ah[mi][3],
                             bh[nj][of], bh[nj][of + 1]);
                    MMA16816(acc[mi][ni], ah[mi][0], ah[mi][1], ah[mi][2], ah[mi][3],
                             bl[nj][of], bl[nj][of + 1]);
                    MMA16816(acc[mi][ni], al[mi][0], al[mi][1], al[mi][2], al[mi][3],
                             bh[nj][of], bh[nj][of + 1]);
                }
        }

        if (more) {
            const int st = ((c + 1) & 1) * ST_ELE;
#pragma unroll
            for (int i = 0; i < 4; i++) {
                uint2 uh, ul;
                cvt_split4(ra[i], uh, ul);
                *(uint2*)(sa_h0 + st + 4 * i) = uh;
                *(uint2*)(sa_l0 + st + 4 * i) = ul;
            }
#pragma unroll
            for (int i = 0; i < 8; i++) {
                uint2 uh, ul;
                cvt_split4(rw[i], uh, ul);
                *(uint2*)(sb_h0 + st + 4 * i) = uh;
                *(uint2*)(sb_l0 + st + 4 * i) = ul;
            }
        }
        __syncthreads();
    }

    // ---- epilogue ----
    const int tr = lane >> 2, tc = (lane & 3) * 2;
#pragma unroll
    for (int mi = 0; mi < 2; mi++) {
        const int m = wm * 32 + mi * 16 + tr;
#pragma unroll
        for (int ni = 0; ni < 4; ni++) {
            const int n = n0 + wn * 32 + ni * 8 + tc;
            float2 r0 = {acc[mi][ni][0], acc[mi][ni][1]};
            float2 r1 = {acc[mi][ni][2], acc[mi][ni][3]};
            *(float2*)&C[(size_t)m * p.ldc + n]       = r0;
            *(float2*)&C[(size_t)(m + 8) * p.ldc + n] = r1;
        }
    }
}

// ---------------- RMSNorm ----------------
__global__ __launch_bounds__(256) void rmsnorm_kernel(
    const float* __restrict__ x, const float* __restrict__ g, float* __restrict__ out)
{
    int row = blockIdx.x, tid = threadIdx.x;
    const float4* xr = (const float4*)(x + (size_t)row * DD);
    const float4* gr = (const float4*)g;
    float4 v[4];
    float ss = 0.f;
#pragma unroll
    for (int i = 0; i < 4; i++) {
        v[i] = xr[tid + 256 * i];
        ss += v[i].x * v[i].x + v[i].y * v[i].y + v[i].z * v[i].z + v[i].w * v[i].w;
    }
#pragma unroll
    for (int o = 16; o; o >>= 1) ss += __shfl_xor_sync(0xffffffffu, ss, o);
    __shared__ float sred[8];
    if ((tid & 31) == 0) sred[tid >> 5] = ss;
    __syncthreads();
    float tot = 0.f;
#pragma unroll
    for (int i = 0; i < 8; i++) tot += sred[i];
    float inv = rsqrtf(tot / (float)DD + 1e-5f);
    float4* orow = (float4*)(out + (size_t)row * DD);
#pragma unroll
    for (int i = 0; i < 4; i++) {
        float4 gv = gr[tid + 256 * i];
        float4 o4;
        o4.x = v[i].x * inv * gv.x;
        o4.y = v[i].y * inv * gv.y;
        o4.z = v[i].z * inv * gv.z;
        o4.w = v[i].w * inv * gv.w;
        orow[tid + 256 * i] = o4;
    }
}

// ---------------- combine QKV split-K partials ----------------
__global__ __launch_bounds__(256) void qkv_combine_kernel()
{
    int idx = blockIdx.x * 256 + threadIdx.x;   // float4 index over BB*DD/4
#pragma unroll
    for (int m = 0; m < 3; m++) {
        float4 s = ((const float4*)g_pt[m * 4 + 0])[idx];
#pragma unroll
        for (int j = 1; j < 4; j++) {
            float4 t = ((const float4*)g_pt[m * 4 + j])[idx];
            s.x += t.x; s.y += t.y; s.z += t.z; s.w += t.w;
        }
        float* dst = (m == 0) ? g_q : (m == 1) ? g_k : g_v;
        ((float4*)dst)[idx] = s;
    }
}

// ---------------- paged flash-decode attention (8 warps) ----------------
__global__ __launch_bounds__(256) void attention_kernel(
    const float* __restrict__ kheap, const float* __restrict__ vheap,
    const int*   __restrict__ btab,  const int*  __restrict__ clens,
    const float* __restrict__ scale_p)
{
    int hh = blockIdx.x, b = blockIdx.y;
    int tid = threadIdx.x, lane = tid & 31, w = tid >> 5;
    int ctx = clens[b];
    float scale = scale_p[0];

    const float4* q4 = (const float4*)(g_q + (size_t)b * DD + hh * HDIM);
    float4 qv = q4[lane];

    float m = -1e30f, l = 0.f;
    float4 acc = {0.f, 0.f, 0.f, 0.f};
    const int last = ctx - 1;

    for (int s = w; s < ctx; s += 8) {
        const float *kp, *vp;
        if (s == last) {
            kp = g_k + (size_t)b * DD + hh * HDIM;
            vp = g_v + (size_t)b * DD + hh * HDIM;
        } else {
            int blk = btab[b * MBSN + (s >> 4)];
            size_t base = (((size_t)blk * HH + hh) * PBS + (s & 15)) * HDIM;
            kp = kheap + base;
            vp = vheap + base;
        }
        float4 kv = *(const float4*)(kp + lane * 4);
        float sc = qv.x * kv.x + qv.y * kv.y + qv.z * kv.z + qv.w * kv.w;
#pragma unroll
        for (int o = 16; o; o >>= 1) sc += __shfl_xor_sync(0xffffffffu, sc, o);
        sc *= scale;
        float mn   = fmaxf(m, sc);
        float corr = expf(m - mn);
        float pw   = expf(sc - mn);
        l = l * corr + pw;
        float4 vv = *(const float4*)(vp + lane * 4);
        acc.x = fmaf(pw, vv.x, acc.x * corr);
        acc.y = fmaf(pw, vv.y, acc.y * corr);
        acc.z = fmaf(pw, vv.z, acc.z * corr);
        acc.w = fmaf(pw, vv.w, acc.w * corr);
        m = mn;
    }

    __shared__ float sm_m[8], sm_l[8];
    __shared__ float sm_acc[8][HDIM];
    if (lane == 0) { sm_m[w] = m; sm_l[w] = l; }
    ((float4*)sm_acc[w])[lane] = acc;
    __syncthreads();

    if (tid < HDIM) {
        int d = tid;
        float M = -1e30f;
#pragma unroll
        for (int i = 0; i < 8; i++) M = fmaxf(M, sm_m[i]);
        float L = 0.f, O = 0.f;
#pragma unroll
        for (int i = 0; i < 8; i++) {
            float e = expf(sm_m[i] - M);
            L += sm_l[i] * e;
            O += sm_acc[i][d] * e;
        }
        g_att[(size_t)b * DD + hh * HDIM + d] = O / L;
    }
}

// ---------------- x2 = sum(g_pt[0..15]) + resid ; h2 = rmsnorm(x2)*g --------
__global__ __launch_bounds__(256) void addreduce_rms_kernel(
    const float* __restrict__ resid, const float* __restrict__ g,
    float* __restrict__ xout, float* __restrict__ hout)
{
    int row = blockIdx.x, tid = threadIdx.x;
    const float4* r4 = (const float4*)(resid + (size_t)row * DD);
    const float4* gr = (const float4*)g;
    float4 v[4];
    float ss = 0.f;
#pragma unroll
    for (int i = 0; i < 4; i++) {
        int idx = tid + 256 * i;
        float4 s = r4[idx];
#pragma unroll
        for (int j = 0; j < 16; j++) {
            float4 t = ((const float4*)(g_pt[j] + (size_t)row * DD))[idx];
            s.x += t.x; s.y += t.y; s.z += t.z; s.w += t.w;
        }
        v[i] = s;
        ss += s.x * s.x + s.y * s.y + s.z * s.z + s.w * s.w;
    }
#pragma unroll
    for (int o = 16; o; o >>= 1) ss += __shfl_xor_sync(0xffffffffu, ss, o);
    __shared__ float sred[8];
    if ((tid & 31) == 0) sred[tid >> 5] = ss;
    __syncthreads();
    float tot = 0.f;
#pragma unroll
    for (int i = 0; i < 8; i++) tot += sred[i];
    float inv = rsqrtf(tot / (float)DD + 1e-5f);
    float4* xo = (float4*)(xout + (size_t)row * DD);
    float4* ho = (float4*)(hout + (size_t)row * DD);
#pragma unroll
    for (int i = 0; i < 4; i++) {
        int idx = tid + 256 * i;
        xo[idx] = v[i];
        float4 gv = gr[idx];
        float4 o4;
        o4.x = v[i].x * inv * gv.x;
        o4.y = v[i].y * inv * gv.y;
        o4.z = v[i].z * inv * gv.z;
        o4.w = v[i].w * inv * gv.w;
        ho[idx] = o4;
    }
}

// ---------------- gate = silu(ff1a+ff1b) * (ff3a+ff3b) ----------------
__global__ __launch_bounds__(256) void silu_mul_kernel()
{
    int idx = blockIdx.x * 256 + threadIdx.x;
    float4 a  = ((const float4*)g_ff1)[idx];
    float4 ab = ((const float4*)g_ff1b)[idx];
    float4 c  = ((const float4*)g_ff3)[idx];
    float4 cb = ((const float4*)g_ff3b)[idx];
    a.x += ab.x; a.y += ab.y; a.z += ab.z; a.w += ab.w;
    c.x += cb.x; c.y += cb.y; c.z += cb.z; c.w += cb.w;
    float4 o;
    o.x = a.x / (1.f + expf(-a.x)) * c.x;
    o.y = a.y / (1.f + expf(-a.y)) * c.y;
    o.z = a.z / (1.f + expf(-a.z)) * c.z;
    o.w = a.w / (1.f + expf(-a.w)) * c.w;
    ((float4*)g_gate)[idx] = o;
}

// ---------------- out = sum(g_pt[0..15]) + resid ----------------
__global__ __launch_bounds__(256) void final_add_kernel(
    const float* __restrict__ resid, float* __restrict__ out)
{
    int idx = blockIdx.x * 256 + threadIdx.x;
    float4 s = ((const float4*)resid)[idx];
#pragma unroll
    for (int j = 0; j < 16; j++) {
        float4 t = ((const float4*)g_pt[j])[idx];
        s.x += t.x; s.y += t.y; s.z += t.z; s.w += t.w;
    }
    ((float4*)out)[idx] = s;
}

// ---------------- host driver ----------------
extern "C" void kernel_launch(void* const* d_in, const int* in_sizes, int n_in,
                              void* d_out, int out_size)
{
    const float* x     = (const float*)d_in[0];
    const float* kheap = (const float*)d_in[1];
    const float* vheap = (const float*)d_in[2];
    const int*   btab  = (const int*)d_in[3];
    const int*   clens = (const int*)d_in[5];
    const float* scale = (const float*)d_in[9];
    const float* Wq    = (const float*)d_in[13];
    const float* Wk    = (const float*)d_in[14];
    const float* Wv    = (const float*)d_in[15];
    const float* Wo    = (const float*)d_in[16];
    const float* W1    = (const float*)d_in[17];
    const float* W2    = (const float*)d_in[18];
    const float* W3    = (const float*)d_in[19];
    const float* g1    = (const float*)d_in[20];
    const float* g2    = (const float*)d_in[21];
    float* out = (float*)d_out;

    float *h, *x2, *h2, *ff1, *ff1b, *ff3, *ff3b, *gate;
    float* pt[16];
    cudaGetSymbolAddress((void**)&h,    g_h);
    cudaGetSymbolAddress((void**)&x2,   g_x2);
    cudaGetSymbolAddress((void**)&h2,   g_h2);
    cudaGetSymbolAddress((void**)&ff1,  g_ff1);
    cudaGetSymbolAddress((void**)&ff1b, g_ff1b);
    cudaGetSymbolAddress((void**)&ff3,  g_ff3);
    cudaGetSymbolAddress((void**)&ff3b, g_ff3b);
    cudaGetSymbolAddress((void**)&gate, g_gate);
    {
        float* base;
        cudaGetSymbolAddress((void**)&base, g_pt);
        for (int j = 0; j < 16; j++) pt[j] = base + (size_t)j * BB * DD;
    }

    const int SMEM = 2 * STAGE_BYTES;   // two stages
    cudaFuncSetAttribute(bf16gemm_kernel,
                         cudaFuncAttributeMaxDynamicSharedMemorySize, SMEM);

    // 1) h = rmsnorm(x) * g1
    rmsnorm_kernel<<<BB, 256>>>(x, g1, h);

    // 2) q,k,v = h @ {Wq,Wk,Wv}^T   split-K=4 each -> 12 jobs, 384 CTAs
    {
        GP p;
        p.A = h; p.lda = DD; p.ldc = DD; p.nbpj = DD / 128;
        const float* Ws[3] = {Wq, Wk, Wv};
        for (int m = 0; m < 3; m++)
            for (int s = 0; s < 4; s++)
                p.jobs[m * 4 + s] = {Ws[m], pt[m * 4 + s], s * (DD / 4), (s + 1) * (DD / 4)};
        bf16gemm_kernel<<<12 * (DD / 128), 256, SMEM>>>(p);
    }
    qkv_combine_kernel<<<(BB * DD) / 4 / 256, 256>>>();

    // 3) paged attention
    attention_kernel<<<dim3(HH, BB), 256>>>(kheap, vheap, btab, clens, scale);

    // 4) att @ Wo^T, split-K=16 -> 512 CTAs
    {
        GP p;
        float* att;
        cudaGetSymbolAddress((void**)&att, g_att);
        p.A = att; p.lda = DD; p.ldc = DD; p.nbpj = DD / 128;
        for (int s = 0; s < 16; s++)
            p.jobs[s] = {Wo, pt[s], s * (DD / 16), (s + 1) * (DD / 16)};
        bf16gemm_kernel<<<16 * (DD / 128), 256, SMEM>>>(p);
    }

    // 5) x2 = sum(pt)+x ; h2 = rmsnorm(x2) * g2
    addreduce_rms_kernel<<<BB, 256>>>(x, g2, x2, h2);

    // 6) ff1 = h2 @ W1^T, ff3 = h2 @ W3^T, split-K=2 each -> 512 CTAs
    {
        GP p;
        p.A = h2; p.lda = DD; p.ldc = DFF; p.nbpj = DFF / 128;
        p.jobs[0] = {W1, ff1,  0,      DD / 2};
        p.jobs[1] = {W1, ff1b, DD / 2, DD};
        p.jobs[2] = {W3, ff3,  0,      DD / 2};
        p.jobs[3] = {W3, ff3b, DD / 2, DD};
        bf16gemm_kernel<<<4 * (DFF / 128), 256, SMEM>>>(p);
    }

    // 7) gate = silu(ff1a+ff1b) * (ff3a+ff3b)
    silu_mul_kernel<<<(BB * DFF) / 4 / 256, 256>>>();

    // 8) gate @ W2^T, split-K=16 -> 512 CTAs
    {
        GP p;
        p.A = gate; p.lda = DFF; p.ldc = DD; p.nbpj = DD / 128;
        for (int s = 0; s < 16; s++)
            p.jobs[s] = {W2, pt[s], s * (DFF / 16), (s + 1) * (DFF / 16)};
        bf16gemm_kernel<<<16 * (DD / 128), 256, SMEM>>>(p);
    }

    // 9) out = sum(pt) + x2
    final_add_kernel<<<(BB * DD) / 4 / 256, 256>>>(x2, out);
}

// round 10
// speedup vs baseline: 2.4745x; 1.0376x over previous
#include <cuda_runtime.h>
#include <cuda_bf16.h>
#include <math.h>
#include <stdint.h>

#define BB   64
#define DD   4096
#define HH   32
#define HDIM 128
#define PBS  16
#define MBSN 32
#define DFF  16384
#define NSLAB 4

// ---------------- device scratch ----------------
__device__ float g_h  [BB * DD];
__device__ float g_q  [BB * DD];
__device__ float g_k  [BB * DD];
__device__ float g_v  [BB * DD];
__device__ float g_att[BB * DD];
__device__ float g_x2 [BB * DD];
__device__ float g_h2 [BB * DD];
__device__ float g_pt [16][BB * DD];     // split-K partials / attention partials
__device__ float g_ff1 [BB * DFF];
__device__ float g_ff1b[BB * DFF];
__device__ float g_ff3 [BB * DFF];
__device__ float g_ff3b[BB * DFF];
__device__ float g_gate[BB * DFF];

// ---------------- PTX helpers ----------------
#define LDSM4(r0, r1, r2, r3, addr)                                          \
    asm volatile("ldmatrix.sync.aligned.m8n8.x4.shared.b16 {%0,%1,%2,%3}, [%4];" \
                 : "=r"(r0), "=r"(r1), "=r"(r2), "=r"(r3) : "r"(addr))

#define MMA16816(d, a0, a1, a2, a3, b0, b1)                                   \
    asm volatile("mma.sync.aligned.m16n8k16.row.col.f32.bf16.bf16.f32 "       \
                 "{%0,%1,%2,%3},{%4,%5,%6,%7},{%8,%9},{%0,%1,%2,%3};"         \
                 : "+f"(d[0]), "+f"(d[1]), "+f"(d[2]), "+f"(d[3])             \
                 : "r"(a0), "r"(a1), "r"(a2), "r"(a3), "r"(b0), "r"(b1))

// split fp32 -> (hi, lo) bf16, packed pairs
__device__ __forceinline__ void cvt_split4(float4 v, uint2& uh, uint2& ul)
{
    __nv_bfloat162 h01 = __floats2bfloat162_rn(v.x, v.y);
    __nv_bfloat162 h23 = __floats2bfloat162_rn(v.z, v.w);
    float lx = v.x - __bfloat162float(__low2bfloat16(h01));
    float ly = v.y - __bfloat162float(__high2bfloat16(h01));
    float lz = v.z - __bfloat162float(__low2bfloat16(h23));
    float lw = v.w - __bfloat162float(__high2bfloat16(h23));
    __nv_bfloat162 l01 = __floats2bfloat162_rn(lx, ly);
    __nv_bfloat162 l23 = __floats2bfloat162_rn(lz, lw);
    uh.x = *(unsigned int*)&h01; uh.y = *(unsigned int*)&h23;
    ul.x = *(unsigned int*)&l01; ul.y = *(unsigned int*)&l23;
}

// ---------------- bf16-split tensor-core GEMM (2-stage pipelined) --------
struct Job { const float* W; float* C; int k0, k1; };
struct GP  { const float* A; int lda; int ldc; int nbpj; Job jobs[16]; };

#define KPAD 72
#define ST_ELE (2 * 64 * KPAD + 2 * 128 * KPAD)
#define STAGE_BYTES (ST_ELE * 2)

__global__ __launch_bounds__(256, 2) void bf16gemm_kernel(GP p)
{
    int job = blockIdx.x / p.nbpj;
    int nb  = blockIdx.x % p.nbpj;
    const float* W = p.jobs[job].W;
    float*       C = p.jobs[job].C;
    const int k0j = p.jobs[job].k0, k1j = p.jobs[job].k1;
    const int n0  = nb * 128;

    extern __shared__ __nv_bfloat16 smem_bf[];

    const int tid = threadIdx.x, lane = tid & 31, w = tid >> 5;
    const int wm = w & 1, wn = w >> 1;

    const int arow = (lane & 7) + (lane & 8);
    const int acol = (lane & 16) >> 1;
    const int brow = (lane & 7) + ((lane & 16) >> 1);
    const int bcol = lane & 8;

    float acc[2][4][4];
#pragma unroll
    for (int i = 0; i < 2; i++)
#pragma unroll
        for (int j = 0; j < 4; j++)
#pragma unroll
            for (int t = 0; t < 4; t++) acc[i][j][t] = 0.f;

    const int lrowA = tid >> 2, lcolA = (tid & 3) * 16;
    const int lrowW = tid >> 1, lcolW = (tid & 1) * 32;
    const float* Arow = p.A + (size_t)lrowA * p.lda + lcolA;
    const float* Wrow = W + (size_t)(n0 + lrowW) * p.lda + lcolW;

    __nv_bfloat16* sa_h0 = smem_bf + lrowA * KPAD + lcolA;
    __nv_bfloat16* sa_l0 = sa_h0 + 64 * KPAD;
    __nv_bfloat16* sb_h0 = smem_bf + 2 * 64 * KPAD + lrowW * KPAD + lcolW;
    __nv_bfloat16* sb_l0 = sb_h0 + 128 * KPAD;

    unsigned int a_base[2], b_base[2];
#pragma unroll
    for (int mi = 0; mi < 2; mi++)
        a_base[mi] = (unsigned int)__cvta_generic_to_shared(
            smem_bf + (wm * 32 + mi * 16 + arow) * KPAD + acol);
#pragma unroll
    for (int nj = 0; nj < 2; nj++)
        b_base[nj] = (unsigned int)__cvta_generic_to_shared(
            smem_bf + 2 * 64 * KPAD + (wn * 32 + nj * 16 + brow) * KPAD + bcol);
    const unsigned int A_LO = 64 * KPAD * 2;
    const unsigned int B_LO = 128 * KPAD * 2;

    const int nch = (k1j - k0j) >> 6;

    float4 ra[4], rw[8];
#pragma unroll
    for (int i = 0; i < 4; i++) ra[i] = *(const float4*)(Arow + k0j + 4 * i);
#pragma unroll
    for (int i = 0; i < 8; i++) rw[i] = *(const float4*)(Wrow + k0j + 4 * i);

#pragma unroll
    for (int i = 0; i < 4; i++) {
        uint2 uh, ul;
        cvt_split4(ra[i], uh, ul);
        *(uint2*)(sa_h0 + 4 * i) = uh;
        *(uint2*)(sa_l0 + 4 * i) = ul;
    }
#pragma unroll
    for (int i = 0; i < 8; i++) {
        uint2 uh, ul;
        cvt_split4(rw[i], uh, ul);
        *(uint2*)(sb_h0 + 4 * i) = uh;
        *(uint2*)(sb_l0 + 4 * i) = ul;
    }
    __syncthreads();

    for (int c = 0; c < nch; c++) {
        const bool more = (c + 1) < nch;
        if (more) {
            const int kn = k0j + (c + 1) * 64;
#pragma unroll
            for (int i = 0; i < 4; i++) ra[i] = *(const float4*)(Arow + kn + 4 * i);
#pragma unroll
            for (int i = 0; i < 8; i++) rw[i] = *(const float4*)(Wrow + kn + 4 * i);
        }

        const unsigned int sb_off = (unsigned int)(c & 1) * STAGE_BYTES;
#pragma unroll
        for (int ks = 0; ks < 4; ks++) {
            const unsigned int koff = sb_off + ks * 16 * 2;
            unsigned int ah[2][4], al[2][4], bh[2][4], bl[2][4];
#pragma unroll
            for (int mi = 0; mi < 2; mi++) {
                LDSM4(ah[mi][0], ah[mi][1], ah[mi][2], ah[mi][3], a_base[mi] + koff);
                LDSM4(al[mi][0], al[mi][1], al[mi][2], al[mi][3], a_base[mi] + koff + A_LO);
            }
#pragma unroll
            for (int nj = 0; nj < 2; nj++) {
                LDSM4(bh[nj][0], bh[nj][1], bh[nj][2], bh[nj][3], b_base[nj] + koff);
                LDSM4(bl[nj][0], bl[nj][1], bl[nj][2], bl[nj][3], b_base[nj] + koff + B_LO);
            }
#pragma unroll
            for (int mi = 0; mi < 2; mi++)
#pragma unroll
                for (int ni = 0; ni < 4; ni++) {
                    const int nj = ni >> 1, of = (ni & 1) * 2;
                    MMA16816(acc[mi][ni], ah[mi][0], ah[mi][1], ah[mi][2], ah[mi][3],
                             bh[nj][of], bh[nj][of + 1]);
                    MMA16816(acc[mi][ni], ah[mi][0], ah[mi][1], ah[mi][2], ah[mi][3],
                             bl[nj][of], bl[nj][of + 1]);
                    MMA16816(acc[mi][ni], al[mi][0], al[mi][1], al[mi][2], al[mi][3],
                             bh[nj][of], bh[nj][of + 1]);
                }
        }

        if (more) {
            const int st = ((c + 1) & 1) * ST_ELE;
#pragma unroll
            for (int i = 0; i < 4; i++) {
                uint2 uh, ul;
                cvt_split4(ra[i], uh, ul);
                *(uint2*)(sa_h0 + st + 4 * i) = uh;
                *(uint2*)(sa_l0 + st + 4 * i) = ul;
            }
#pragma unroll
            for (int i = 0; i < 8; i++) {
                uint2 uh, ul;
                cvt_split4(rw[i], uh, ul);
                *(uint2*)(sb_h0 + st + 4 * i) = uh;
                *(uint2*)(sb_l0 + st + 4 * i) = ul;
            }
        }
        __syncthreads();
    }

    const int tr = lane >> 2, tc = (lane & 3) * 2;
#pragma unroll
    for (int mi = 0; mi < 2; mi++) {
        const int m = wm * 32 + mi * 16 + tr;
#pragma unroll
        for (int ni = 0; ni < 4; ni++) {
            const int n = n0 + wn * 32 + ni * 8 + tc;
            float2 r0 = {acc[mi][ni][0], acc[mi][ni][1]};
            float2 r1 = {acc[mi][ni][2], acc[mi][ni][3]};
            *(float2*)&C[(size_t)m * p.ldc + n]       = r0;
            *(float2*)&C[(size_t)(m + 8) * p.ldc + n] = r1;
        }
    }
}

// ---------------- RMSNorm ----------------
__global__ __launch_bounds__(256) void rmsnorm_kernel(
    const float* __restrict__ x, const float* __restrict__ g, float* __restrict__ out)
{
    int row = blockIdx.x, tid = threadIdx.x;
    const float4* xr = (const float4*)(x + (size_t)row * DD);
    const float4* gr = (const float4*)g;
    float4 v[4];
    float ss = 0.f;
#pragma unroll
    for (int i = 0; i < 4; i++) {
        v[i] = xr[tid + 256 * i];
        ss += v[i].x * v[i].x + v[i].y * v[i].y + v[i].z * v[i].z + v[i].w * v[i].w;
    }
#pragma unroll
    for (int o = 16; o; o >>= 1) ss += __shfl_xor_sync(0xffffffffu, ss, o);
    __shared__ float sred[8];
    if ((tid & 31) == 0) sred[tid >> 5] = ss;
    __syncthreads();
    float tot = 0.f;
#pragma unroll
    for (int i = 0; i < 8; i++) tot += sred[i];
    float inv = rsqrtf(tot / (float)DD + 1e-5f);
    float4* orow = (float4*)(out + (size_t)row * DD);
#pragma unroll
    for (int i = 0; i < 4; i++) {
        float4 gv = gr[tid + 256 * i];
        float4 o4;
        o4.x = v[i].x * inv * gv.x;
        o4.y = v[i].y * inv * gv.y;
        o4.z = v[i].z * inv * gv.z;
        o4.w = v[i].w * inv * gv.w;
        orow[tid + 256 * i] = o4;
    }
}

// ---------------- combine QKV split-K partials ----------------
__global__ __launch_bounds__(256) void qkv_combine_kernel()
{
    int idx = blockIdx.x * 256 + threadIdx.x;
#pragma unroll
    for (int m = 0; m < 3; m++) {
        float4 s = ((const float4*)g_pt[m * 4 + 0])[idx];
#pragma unroll
        for (int j = 1; j < 4; j++) {
            float4 t = ((const float4*)g_pt[m * 4 + j])[idx];
            s.x += t.x; s.y += t.y; s.z += t.z; s.w += t.w;
        }
        float* dst = (m == 0) ? g_q : (m == 1) ? g_k : g_v;
        ((float4*)dst)[idx] = s;
    }
}

// ---------------- flash-decode attention: slab partial ----------------
// grid (HH, BB, NSLAB), block 256. Slab z covers tokens [z*128, z*128+128).
// Partials: m at g_pt[0][z*2048+bh], l at g_pt[0][8192+z*2048+bh],
//           unnormalized acc at g_pt[4+z][bh*128+d].
__global__ __launch_bounds__(256) void attn_partial_kernel(
    const float* __restrict__ kheap, const float* __restrict__ vheap,
    const int*   __restrict__ btab,  const int*  __restrict__ clens,
    const float* __restrict__ scale_p)
{
    const int hh = blockIdx.x, b = blockIdx.y, slab = blockIdx.z;
    const int ctx = clens[b];
    const int base = slab * 128;
    if (base >= ctx) return;
    const int send = min(ctx, base + 128);

    const int tid = threadIdx.x, lane = tid & 31, w = tid >> 5;
    const float scale = scale_p[0];
    const int last = ctx - 1;

    const float4 qv = ((const float4*)(g_q + (size_t)b * DD + hh * HDIM))[lane];

    float m = -1e30f, l = 0.f;
    float4 acc = {0.f, 0.f, 0.f, 0.f};

    for (int s = base + w; s < send; s += 8) {
        const float *kp, *vp;
        if (s == last) {
            kp = g_k + (size_t)b * DD + hh * HDIM;
            vp = g_v + (size_t)b * DD + hh * HDIM;
        } else {
            int blk = btab[b * MBSN + (s >> 4)];
            size_t hbase = (((size_t)blk * HH + hh) * PBS + (s & 15)) * HDIM;
            kp = kheap + hbase;
            vp = vheap + hbase;
        }
        // issue K and V loads together (independent of the reduce chain)
        float4 kv = *(const float4*)(kp + lane * 4);
        float4 vv = *(const float4*)(vp + lane * 4);
        float sc = qv.x * kv.x + qv.y * kv.y + qv.z * kv.z + qv.w * kv.w;
#pragma unroll
        for (int o = 16; o; o >>= 1) sc += __shfl_xor_sync(0xffffffffu, sc, o);
        sc *= scale;
        float mn   = fmaxf(m, sc);
        float corr = expf(m - mn);
        float pw   = expf(sc - mn);
        l = l * corr + pw;
        acc.x = fmaf(pw, vv.x, acc.x * corr);
        acc.y = fmaf(pw, vv.y, acc.y * corr);
        acc.z = fmaf(pw, vv.z, acc.z * corr);
        acc.w = fmaf(pw, vv.w, acc.w * corr);
        m = mn;
    }

    __shared__ float sm_m[8], sm_l[8];
    __shared__ float sm_acc[8][HDIM];
    if (lane == 0) { sm_m[w] = m; sm_l[w] = l; }
    ((float4*)sm_acc[w])[lane] = acc;
    __syncthreads();

    if (tid < HDIM) {
        const int d = tid;
        float M = -1e30f;
#pragma unroll
        for (int i = 0; i < 8; i++) M = fmaxf(M, sm_m[i]);
        float L = 0.f, O = 0.f;
#pragma unroll
        for (int i = 0; i < 8; i++) {
            float e = expf(sm_m[i] - M);
            L += sm_l[i] * e;
            O += sm_acc[i][d] * e;
        }
        const int bh = b * HH + hh;
        if (d == 0) {
            g_pt[0][slab * 2048 + bh]        = M;
            g_pt[0][8192 + slab * 2048 + bh] = L;
        }
        g_pt[4 + slab][(size_t)bh * HDIM + d] = O;   // unnormalized, frame M
    }
}

// ---------------- flash-decode attention: slab reduce ----------------
__global__ __launch_bounds__(128) void attn_reduce_kernel(const int* __restrict__ clens)
{
    const int hh = blockIdx.x, b = blockIdx.y, d = threadIdx.x;
    const int ctx = clens[b];
    const int ns = (ctx + 127) >> 7;
    const int bh = b * HH + hh;

    float M = -1e30f;
    for (int s = 0; s < ns; s++) M = fmaxf(M, g_pt[0][s * 2048 + bh]);
    float L = 0.f, O = 0.f;
    for (int s = 0; s < ns; s++) {
        float e = expf(g_pt[0][s * 2048 + bh] - M);
        L += g_pt[0][8192 + s * 2048 + bh] * e;
        O += g_pt[4 + s][(size_t)bh * HDIM + d] * e;
    }
    g_att[(size_t)b * DD + hh * HDIM + d] = O / L;
}

// ---------------- x2 = sum(g_pt[0..15]) + resid ; h2 = rmsnorm(x2)*g --------
__global__ __launch_bounds__(256) void addreduce_rms_kernel(
    const float* __restrict__ resid, const float* __restrict__ g,
    float* __restrict__ xout, float* __restrict__ hout)
{
    int row = blockIdx.x, tid = threadIdx.x;
    const float4* r4 = (const float4*)(resid + (size_t)row * DD);
    const float4* gr = (const float4*)g;
    float4 v[4];
    float ss = 0.f;
#pragma unroll
    for (int i = 0; i < 4; i++) {
        int idx = tid + 256 * i;
        float4 s = r4[idx];
#pragma unroll
        for (int j = 0; j < 16; j++) {
            float4 t = ((const float4*)(g_pt[j] + (size_t)row * DD))[idx];
            s.x += t.x; s.y += t.y; s.z += t.z; s.w += t.w;
        }
        v[i] = s;
        ss += s.x * s.x + s.y * s.y + s.z * s.z + s.w * s.w;
    }
#pragma unroll
    for (int o = 16; o; o >>= 1) ss += __shfl_xor_sync(0xffffffffu, ss, o);
    __shared__ float sred[8];
    if ((tid & 31) == 0) sred[tid >> 5] = ss;
    __syncthreads();
    float tot = 0.f;
#pragma unroll
    for (int i = 0; i < 8; i++) tot += sred[i];
    float inv = rsqrtf(tot / (float)DD + 1e-5f);
    float4* xo = (float4*)(xout + (size_t)row * DD);
    float4* ho = (float4*)(hout + (size_t)row * DD);
#pragma unroll
    for (int i = 0; i < 4; i++) {
        int idx = tid + 256 * i;
        xo[idx] = v[i];
        float4 gv = gr[idx];
        float4 o4;
        o4.x = v[i].x * inv * gv.x;
        o4.y = v[i].y * inv * gv.y;
        o4.z = v[i].z * inv * gv.z;
        o4.w = v[i].w * inv * gv.w;
        ho[idx] = o4;
    }
}

// ---------------- gate = silu(ff1a+ff1b) * (ff3a+ff3b) ----------------
__global__ __launch_bounds__(256) void silu_mul_kernel()
{
    int idx = blockIdx.x * 256 + threadIdx.x;
    float4 a  = ((const float4*)g_ff1)[idx];
    float4 ab = ((const float4*)g_ff1b)[idx];
    float4 c  = ((const float4*)g_ff3)[idx];
    float4 cb = ((const float4*)g_ff3b)[idx];
    a.x += ab.x; a.y += ab.y; a.z += ab.z; a.w += ab.w;
    c.x += cb.x; c.y += cb.y; c.z += cb.z; c.w += cb.w;
    float4 o;
    o.x = a.x / (1.f + expf(-a.x)) * c.x;
    o.y = a.y / (1.f + expf(-a.y)) * c.y;
    o.z = a.z / (1.f + expf(-a.z)) * c.z;
    o.w = a.w / (1.f + expf(-a.w)) * c.w;
    ((float4*)g_gate)[idx] = o;
}

// ---------------- out = sum(g_pt[0..15]) + resid ----------------
__global__ __launch_bounds__(256) void final_add_kernel(
    const float* __restrict__ resid, float* __restrict__ out)
{
    int idx = blockIdx.x * 256 + threadIdx.x;
    float4 s = ((const float4*)resid)[idx];
#pragma unroll
    for (int j = 0; j < 16; j++) {
        float4 t = ((const float4*)g_pt[j])[idx];
        s.x += t.x; s.y += t.y; s.z += t.z; s.w += t.w;
    }
    ((float4*)out)[idx] = s;
}

// ---------------- host driver ----------------
extern "C" void kernel_launch(void* const* d_in, const int* in_sizes, int n_in,
                              void* d_out, int out_size)
{
    const float* x     = (const float*)d_in[0];
    const float* kheap = (const float*)d_in[1];
    const float* vheap = (const float*)d_in[2];
    const int*   btab  = (const int*)d_in[3];
    const int*   clens = (const int*)d_in[5];
    const float* scale = (const float*)d_in[9];
    const float* Wq    = (const float*)d_in[13];
    const float* Wk    = (const float*)d_in[14];
    const float* Wv    = (const float*)d_in[15];
    const float* Wo    = (const float*)d_in[16];
    const float* W1    = (const float*)d_in[17];
    const float* W2    = (const float*)d_in[18];
    const float* W3    = (const float*)d_in[19];
    const float* g1    = (const float*)d_in[20];
    const float* g2    = (const float*)d_in[21];
    float* out = (float*)d_out;

    float *h, *x2, *h2, *ff1, *ff1b, *ff3, *ff3b, *gate, *att;
    float* pt[16];
    cudaGetSymbolAddress((void**)&h,    g_h);
    cudaGetSymbolAddress((void**)&x2,   g_x2);
    cudaGetSymbolAddress((void**)&h2,   g_h2);
    cudaGetSymbolAddress((void**)&ff1,  g_ff1);
    cudaGetSymbolAddress((void**)&ff1b, g_ff1b);
    cudaGetSymbolAddress((void**)&ff3,  g_ff3);
    cudaGetSymbolAddress((void**)&ff3b, g_ff3b);
    cudaGetSymbolAddress((void**)&gate, g_gate);
    cudaGetSymbolAddress((void**)&att,  g_att);
    {
        float* base;
        cudaGetSymbolAddress((void**)&base, g_pt);
        for (int j = 0; j < 16; j++) pt[j] = base + (size_t)j * BB * DD;
    }

    const int SMEM = 2 * STAGE_BYTES;
    cudaFuncSetAttribute(bf16gemm_kernel,
                         cudaFuncAttributeMaxDynamicSharedMemorySize, SMEM);

    // 1) h = rmsnorm(x) * g1
    rmsnorm_kernel<<<BB, 256>>>(x, g1, h);

    // 2) q,k,v = h @ {Wq,Wk,Wv}^T   split-K=4 each -> 384 CTAs
    {
        GP p;
        p.A = h; p.lda = DD; p.ldc = DD; p.nbpj = DD / 128;
        const float* Ws[3] = {Wq, Wk, Wv};
        for (int m = 0; m < 3; m++)
            for (int s = 0; s < 4; s++)
                p.jobs[m * 4 + s] = {Ws[m], pt[m * 4 + s], s * (DD / 4), (s + 1) * (DD / 4)};
        bf16gemm_kernel<<<12 * (DD / 128), 256, SMEM>>>(p);
    }
    qkv_combine_kernel<<<(BB * DD) / 4 / 256, 256>>>();

    // 3) flash-decode attention: slab partials + reduce
    attn_partial_kernel<<<dim3(HH, BB, NSLAB), 256>>>(kheap, vheap, btab, clens, scale);
    attn_reduce_kernel<<<dim3(HH, BB), 128>>>(clens);

    // 4) att @ Wo^T, split-K=16 -> 512 CTAs
    {
        GP p;
        p.A = att; p.lda = DD; p.ldc = DD; p.nbpj = DD / 128;
        for (int s = 0; s < 16; s++)
            p.jobs[s] = {Wo, pt[s], s * (DD / 16), (s + 1) * (DD / 16)};
        bf16gemm_kernel<<<16 * (DD / 128), 256, SMEM>>>(p);
    }

    // 5) x2 = sum(pt)+x ; h2 = rmsnorm(x2) * g2
    addreduce_rms_kernel<<<BB, 256>>>(x, g2, x2, h2);

    // 6) ff1 = h2 @ W1^T, ff3 = h2 @ W3^T, split-K=2 each -> 512 CTAs
    {
        GP p;
        p.A = h2; p.lda = DD; p.ldc = DFF; p.nbpj = DFF / 128;
        p.jobs[0] = {W1, ff1,  0,      DD / 2};
        p.jobs[1] = {W1, ff1b, DD / 2, DD};
        p.jobs[2] = {W3, ff3,  0,      DD / 2};
        p.jobs[3] = {W3, ff3b, DD / 2, DD};
        bf16gemm_kernel<<<4 * (DFF / 128), 256, SMEM>>>(p);
    }

    // 7) gate = silu(ff1a+ff1b) * (ff3a+ff3b)
    silu_mul_kernel<<<(BB * DFF) / 4 / 256, 256>>>();

    // 8) gate @ W2^T, split-K=16 -> 512 CTAs
    {
        GP p;
        p.A = gate; p.lda = DFF; p.ldc = DD; p.nbpj = DD / 128;
        for (int s = 0; s < 16; s++)
            p.jobs[s] = {W2, pt[s], s * (DFF / 16), (s + 1) * (DFF / 16)};
        bf16gemm_kernel<<<16 * (DD / 128), 256, SMEM>>>(p);
    }

    // 9) out = sum(pt) + x2
    final_add_kernel<<<(BB * DD) / 4 / 256, 256>>>(x2, out);
}